// round 8
// baseline (speedup 1.0000x reference)
#include <cuda_runtime.h>
#include <cuda_bf16.h>
#include <cstdint>

#define Bc 2
#define Lc 4096
#define Hc 8
#define Dc 64
#define Mc 128
#define BH 16
#define NCH 64

typedef unsigned long long ull;

// ---- f32x2 helpers (proj/chunk SIMT kernels) ----
__device__ __forceinline__ ull pack2(float a, float b) {
    ull r; asm("mov.b64 %0, {%1, %2};" : "=l"(r) : "r"(__float_as_uint(a)), "r"(__float_as_uint(b))); return r;
}
__device__ __forceinline__ ull bcast2(float a) { return pack2(a, a); }
__device__ __forceinline__ void unpack2(ull v, float& a, float& b) {
    unsigned x, y; asm("mov.b64 {%0, %1}, %2;" : "=r"(x), "=r"(y) : "l"(v));
    a = __uint_as_float(x); b = __uint_as_float(y);
}
__device__ __forceinline__ void ffma2(ull& acc, ull a, ull b) {
    asm("fma.rn.f32x2 %0, %1, %2, %0;" : "+l"(acc) : "l"(a), "l"(b));
}

// ---- scratch ----
__device__ float g_qp[BH * Lc * Mc];            // [bh][chunk][r64][m128]
__device__ float g_kp[BH * Lc * Mc];            // [bh][chunk][c64][m128]
__device__ float g_state[BH * NCH * Dc * Mc];   // per chunk [m128][d64]
__device__ float g_ksum[BH * NCH * Mc];

// ---- warp-mma helpers (standard PTX, no 'a' features) ----
__device__ __forceinline__ uint32_t smem_u32(const void* p) {
    uint32_t a; asm("{ .reg .u64 t; cvta.to.shared.u64 t, %1; cvt.u32.u64 %0, t; }" : "=r"(a) : "l"(p)); return a;
}
__device__ __forceinline__ void ldsm4(uint32_t addr, uint32_t& r0, uint32_t& r1, uint32_t& r2, uint32_t& r3) {
    asm volatile("ldmatrix.sync.aligned.m8n8.x4.shared.b16 {%0,%1,%2,%3}, [%4];"
        : "=r"(r0), "=r"(r1), "=r"(r2), "=r"(r3) : "r"(addr));
}
__device__ __forceinline__ void ldsm4t(uint32_t addr, uint32_t& r0, uint32_t& r1, uint32_t& r2, uint32_t& r3) {
    asm volatile("ldmatrix.sync.aligned.m8n8.x4.trans.shared.b16 {%0,%1,%2,%3}, [%4];"
        : "=r"(r0), "=r"(r1), "=r"(r2), "=r"(r3) : "r"(addr));
}
__device__ __forceinline__ void mma16816(float* c, const uint32_t* a, uint32_t b0, uint32_t b1) {
    asm volatile("mma.sync.aligned.m16n8k16.row.col.f32.bf16.bf16.f32 "
        "{%0,%1,%2,%3}, {%4,%5,%6,%7}, {%8,%9}, {%0,%1,%2,%3};"
        : "+f"(c[0]), "+f"(c[1]), "+f"(c[2]), "+f"(c[3])
        : "r"(a[0]), "r"(a[1]), "r"(a[2]), "r"(a[3]), "r"(b0), "r"(b1));
}
// bf16 hi/lo split of a float pair -> packed bf16x2
__device__ __forceinline__ void split2(float a, float b, uint32_t& h, uint32_t& l) {
    __nv_bfloat162 hv = __floats2bfloat162_rn(a, b);
    float ra = a - __bfloat162float(__low2bfloat16(hv));
    float rb = b - __bfloat162float(__high2bfloat16(hv));
    __nv_bfloat162 lv = __floats2bfloat162_rn(ra, rb);
    h = *(uint32_t*)&hv; l = *(uint32_t*)&lv;
}

// ---------------------------------------------------------------------------
// Kernel 1: projection.  grid 2048: qk*1024 + bh*64 + chunk. Out: [r][m] tiles.
// ---------------------------------------------------------------------------
#define PJ_PT 132
#define PJ_RT 68
#define PJ_SMEM (64*PJ_PT + 64*PJ_RT)
__global__ void __launch_bounds__(256, 2)
proj_kernel(const float* __restrict__ qg, const float* __restrict__ kg, const float* __restrict__ pg)
{
    extern __shared__ float psm[];
    float* p_T    = psm;
    float* rows_T = psm + 64 * PJ_PT;
    int bid = blockIdx.x, qk = bid >> 10, bh = (bid >> 6) & 15, ck = bid & 63;
    int b = bh >> 3, h = bh & 7;
    const float* inp = qk ? kg : qg;
    float* outp = (qk ? g_kp : g_qp) + ((size_t)bh * Lc + ck * 64) * Mc;
    int tid = threadIdx.x;

    const float4* p4 = (const float4*)pg;
    #pragma unroll
    for (int t = tid; t < 2048; t += 256) {
        float4 v = p4[t];
        int m = t >> 4, d0 = (t & 15) * 4;
        p_T[(d0+0)*PJ_PT + m] = v.x; p_T[(d0+1)*PJ_PT + m] = v.y;
        p_T[(d0+2)*PJ_PT + m] = v.z; p_T[(d0+3)*PJ_PT + m] = v.w;
    }
    #pragma unroll
    for (int t = tid; t < 1024; t += 256) {
        int r = t >> 4, d0 = (t & 15) * 4;
        const float4* src = (const float4*)(inp + (((size_t)b * Lc + ck*64 + r) * Hc + h) * Dc);
        float4 v = src[t & 15];
        rows_T[(d0+0)*PJ_RT + r] = v.x; rows_T[(d0+1)*PJ_RT + r] = v.y;
        rows_T[(d0+2)*PJ_RT + r] = v.z; rows_T[(d0+3)*PJ_RT + r] = v.w;
    }
    __syncthreads();

    int mg = tid & 31, rg = tid >> 5;
    int m0 = 4 * mg, r0 = 8 * rg;
    ull acc2[4][4];
    #pragma unroll
    for (int a = 0; a < 4; a++) { acc2[a][0]=0; acc2[a][1]=0; acc2[a][2]=0; acc2[a][3]=0; }
    #pragma unroll 4
    for (int d = 0; d < 64; d++) {
        float4 pv  = *(const float4*)&p_T[d * PJ_PT + m0];
        float4 rv0 = *(const float4*)&rows_T[d * PJ_RT + r0];
        float4 rv1 = *(const float4*)&rows_T[d * PJ_RT + r0 + 4];
        ull rp[4] = { pack2(rv0.x,rv0.y), pack2(rv0.z,rv0.w), pack2(rv1.x,rv1.y), pack2(rv1.z,rv1.w) };
        ull pb[4] = { bcast2(pv.x), bcast2(pv.y), bcast2(pv.z), bcast2(pv.w) };
        #pragma unroll
        for (int a = 0; a < 4; a++)
            #pragma unroll
            for (int c = 0; c < 4; c++) ffma2(acc2[a][c], rp[a], pb[c]);
    }
    const float ratio = 0.08838834764831845f;
    #pragma unroll
    for (int a = 0; a < 4; a++) {
        float lo[4], hi[4];
        #pragma unroll
        for (int c = 0; c < 4; c++) {
            unpack2(acc2[a][c], lo[c], hi[c]);
            lo[c] *= ratio; lo[c] = (lo[c] > 0.f ? lo[c] : 0.f) + 1e-3f;
            hi[c] *= ratio; hi[c] = (hi[c] > 0.f ? hi[c] : 0.f) + 1e-3f;
        }
        *(float4*)&outp[(r0 + 2*a    ) * Mc + m0] = make_float4(lo[0], lo[1], lo[2], lo[3]);
        *(float4*)&outp[(r0 + 2*a + 1) * Mc + m0] = make_float4(hi[0], hi[1], hi[2], hi[3]);
    }
}

// ---------------------------------------------------------------------------
// Kernel 2: S[m][d] = sum_c K[c][m] V[c][d], z[m].  K tiles [c][m].
// ---------------------------------------------------------------------------
#define CK_KP 132
#define CK_VP 68
#define CK_SMEM (64*CK_KP + 64*CK_VP)
__global__ void __launch_bounds__(256, 2)
chunk_kernel(const float* __restrict__ vg)
{
    extern __shared__ float csm[];
    float* k_s = csm;
    float* v_s = csm + 64 * CK_KP;
    int tid = threadIdx.x, bh = blockIdx.x >> 6, c = blockIdx.x & 63;
    int b = bh >> 3, h = bh & 7;

    const float4* ksrc = (const float4*)&g_kp[((size_t)bh * Lc + c * 64) * Mc];
    #pragma unroll
    for (int t = tid; t < 2048; t += 256) {
        float4 w = ksrc[t];
        int cc = t >> 5, m0 = (t & 31) * 4;
        *(float4*)&k_s[cc * CK_KP + m0] = w;
    }
    #pragma unroll
    for (int t = tid; t < 1024; t += 256) {
        int row = t >> 4, col = t & 15;
        const float4* src = (const float4*)(vg + (((size_t)b * Lc + c*64 + row) * Hc + h) * Dc);
        *(float4*)&v_s[row * CK_VP + col * 4] = src[col];
    }
    __syncthreads();

    int mg = tid & 31, dg = tid >> 5;
    int d0 = dg * 8;
    ull acc2[4][4];
    #pragma unroll
    for (int i = 0; i < 4; i++) { acc2[i][0]=0; acc2[i][1]=0; acc2[i][2]=0; acc2[i][3]=0; }
    #pragma unroll 4
    for (int cc = 0; cc < 64; cc++) {
        ulonglong2 va = *(const ulonglong2*)&v_s[cc * CK_VP + d0];
        ulonglong2 vb = *(const ulonglong2*)&v_s[cc * CK_VP + d0 + 4];
        #pragma unroll
        for (int i = 0; i < 4; i++) {
            ull kb = bcast2(k_s[cc * CK_KP + mg + 32 * i]);
            ffma2(acc2[i][0], kb, va.x); ffma2(acc2[i][1], kb, va.y);
            ffma2(acc2[i][2], kb, vb.x); ffma2(acc2[i][3], kb, vb.y);
        }
    }
    float* Sp = &g_state[(size_t)blockIdx.x * (Dc * Mc)];
    #pragma unroll
    for (int i = 0; i < 4; i++) {
        int m = mg + 32 * i;
        float f0,f1,f2,f3,f4,f5,f6,f7;
        unpack2(acc2[i][0],f0,f1); unpack2(acc2[i][1],f2,f3);
        unpack2(acc2[i][2],f4,f5); unpack2(acc2[i][3],f6,f7);
        *(float4*)&Sp[m * 64 + d0]     = make_float4(f0,f1,f2,f3);
        *(float4*)&Sp[m * 64 + d0 + 4] = make_float4(f4,f5,f6,f7);
    }
    if (tid < 128) {
        float z = 0.f;
        #pragma unroll 8
        for (int cc = 0; cc < 64; cc++) z += k_s[cc * CK_KP + tid];
        g_ksum[(size_t)blockIdx.x * Mc + tid] = z;
    }
}

// ---------------------------------------------------------------------------
// Kernel 3: exclusive prefix over chunks (in place).
// ---------------------------------------------------------------------------
__global__ void prefix_kernel()
{
    int bh = blockIdx.x >> 5, slice = blockIdx.x & 31;
    int e = slice * 256 + threadIdx.x;
    size_t base = (size_t)bh * NCH * (Dc * Mc) + e;
    float acc = 0.f;
    #pragma unroll 1
    for (int c0 = 0; c0 < 64; c0 += 8) {
        float v[8];
        #pragma unroll
        for (int u = 0; u < 8; u++) v[u] = g_state[base + (size_t)(c0 + u) * (Dc * Mc)];
        #pragma unroll
        for (int u = 0; u < 8; u++) { g_state[base + (size_t)(c0 + u) * (Dc * Mc)] = acc; acc += v[u]; }
    }
    if (slice == 0 && threadIdx.x < 128) {
        size_t kb = (size_t)bh * NCH * Mc + threadIdx.x;
        float a2 = 0.f;
        #pragma unroll 1
        for (int c = 0; c < 64; c++) { float t = g_ksum[kb + (size_t)c * Mc]; g_ksum[kb + (size_t)c * Mc] = a2; a2 += t; }
    }
}

// ---------------------------------------------------------------------------
// Kernel 4: warp-MMA bf16-split out_kernel.  grid 1024, 256 threads (8 warps).
// Warp (rw, cw): rows 16*rw..+15, cols 32*cw..+31 of the 64x64 outputs.
// ---------------------------------------------------------------------------
#define QPB 272   // byte pitch, 128-col bf16 tiles (17 x 16B chunks)
#define TPB 144   // byte pitch, 64-col bf16 tiles (9 x 16B chunks)
#define QH_O 0
#define QL_O 17408
#define KH_O 34816
#define KL_O 52224
#define SH_O 69632
#define SL_O 88064
#define VH_O 106496
#define VL_O 115712
#define AH_O 124928
#define AL_O 134144
#define KS_O 143360
#define DEN_O 143872
#define OUT_SMEM 144128

__global__ void __launch_bounds__(256, 1)
out_kernel(const float* __restrict__ vg, float* __restrict__ outg)
{
    extern __shared__ __align__(128) char smb[];
    uint32_t sb = smem_u32(smb);
    float* ks_s  = (float*)(smb + KS_O);
    float* den_s = (float*)(smb + DEN_O);

    int tid = threadIdx.x, lane = tid & 31, wid = tid >> 5;
    int bh = blockIdx.x >> 6, c = blockIdx.x & 63;
    int b = bh >> 3, h = bh & 7;

    const float* qt = g_qp + (size_t)blockIdx.x * (64 * Mc);
    const float* kt = g_kp + (size_t)blockIdx.x * (64 * Mc);
    const float* st = g_state + (size_t)blockIdx.x * (Mc * Dc);

    // ---- split loads (all conflict-free uint32 stores) ----
    for (int t = tid; t < 4096; t += 256) {        // Q and K: [r][m]
        int r = t >> 6, m2 = (t & 63) * 2;
        float2 qv = *(const float2*)(qt + r * Mc + m2);
        float2 kv = *(const float2*)(kt + r * Mc + m2);
        uint32_t hq, lq, hk, lk;
        split2(qv.x, qv.y, hq, lq); split2(kv.x, kv.y, hk, lk);
        uint32_t off = r * QPB + m2 * 2;
        *(uint32_t*)(smb + QH_O + off) = hq; *(uint32_t*)(smb + QL_O + off) = lq;
        *(uint32_t*)(smb + KH_O + off) = hk; *(uint32_t*)(smb + KL_O + off) = lk;
    }
    for (int t = tid; t < 4096; t += 256) {        // S: [m][d]
        int m = t >> 5, d2 = (t & 31) * 2;
        float2 sv = *(const float2*)(st + m * Dc + d2);
        uint32_t hs, ls; split2(sv.x, sv.y, hs, ls);
        uint32_t off = m * TPB + d2 * 2;
        *(uint32_t*)(smb + SH_O + off) = hs; *(uint32_t*)(smb + SL_O + off) = ls;
    }
    for (int t = tid; t < 2048; t += 256) {        // V: [j][d]
        int j = t >> 5, d2 = (t & 31) * 2;
        float2 vv = *(const float2*)(vg + (((size_t)b * Lc + c*64 + j) * Hc + h) * Dc + d2);
        uint32_t hv, lv; split2(vv.x, vv.y, hv, lv);
        uint32_t off = j * TPB + d2 * 2;
        *(uint32_t*)(smb + VH_O + off) = hv; *(uint32_t*)(smb + VL_O + off) = lv;
    }
    if (tid < 128) ks_s[tid] = g_ksum[(size_t)blockIdx.x * Mc + tid];
    __syncthreads();

    // den init: Q . ksum (fp32, from global Q rows)
    if (tid < 64) {
        const float4* qr = (const float4*)(qt + tid * Mc);
        float qd = 0.f;
        #pragma unroll 8
        for (int m4 = 0; m4 < 32; m4++) {
            float4 q4 = qr[m4];
            qd += q4.x * ks_s[4*m4] + q4.y * ks_s[4*m4+1] + q4.z * ks_s[4*m4+2] + q4.w * ks_s[4*m4+3];
        }
        den_s[tid] = qd;
    }
    __syncthreads();

    int rw = wid & 3, cw = wid >> 2;
    int i0 = 16 * rw, n0 = 32 * cw;
    int q4i = lane >> 3, rr = lane & 7;   // ldmatrix lane decomposition

    // per-lane fragment row bases
    uint32_t aRowQ = sb + QH_O + (i0 + (lane & 15)) * QPB + (lane >> 4) * 16;
    uint32_t bRowK = sb + KH_O + (n0 + 8 * (q4i >> 1) + rr) * QPB + (q4i & 1) * 16;
    uint32_t aRowA = sb + AH_O + (i0 + (lane & 15)) * TPB + (lane >> 4) * 16;
    uint32_t bRowV = sb + VH_O + (8 * (q4i & 1) + rr) * TPB + (n0 + 8 * (q4i >> 1)) * 2;
    uint32_t bRowS = sb + SH_O + (8 * (q4i & 1) + rr) * TPB + (n0 + 8 * (q4i >> 1)) * 2;

    // ---- GEMM1: A = Q K^T (3 split passes) ----
    float cA[4][4];
    #pragma unroll
    for (int nt = 0; nt < 4; nt++) { cA[nt][0]=0; cA[nt][1]=0; cA[nt][2]=0; cA[nt][3]=0; }
    {
        const int dA[3] = {0, 0, QL_O - QH_O};
        const int dB[3] = {0, KL_O - KH_O, 0};
        #pragma unroll
        for (int p = 0; p < 3; p++) {
            uint32_t aB = aRowQ + dA[p], bB = bRowK + dB[p];
            #pragma unroll
            for (int k0 = 0; k0 < 128; k0 += 16) {
                uint32_t a[4], b0,b1,b2,b3,b4,b5,b6,b7;
                ldsm4(aB + k0*2, a[0], a[1], a[2], a[3]);
                ldsm4(bB + k0*2, b0, b1, b2, b3);
                ldsm4(bB + 16*QPB + k0*2, b4, b5, b6, b7);
                mma16816(cA[0], a, b0, b1);
                mma16816(cA[1], a, b2, b3);
                mma16816(cA[2], a, b4, b5);
                mma16816(cA[3], a, b6, b7);
            }
        }
    }

    // ---- mask, rowsum, split-store A ----
    {
        int r0g = i0 + (lane >> 2);
        int cb  = n0 + 2 * (lane & 3);
        float rs0 = 0.f, rs1 = 0.f;
        #pragma unroll
        for (int nt = 0; nt < 4; nt++) {
            int j0 = cb + 8 * nt;
            float x0 = (j0     <= r0g    ) ? cA[nt][0] : 0.f;
            float x1 = (j0 + 1 <= r0g    ) ? cA[nt][1] : 0.f;
            float x2 = (j0     <= r0g + 8) ? cA[nt][2] : 0.f;
            float x3 = (j0 + 1 <= r0g + 8) ? cA[nt][3] : 0.f;
            rs0 += x0 + x1; rs1 += x2 + x3;
            uint32_t h0, l0, h1, l1;
            split2(x0, x1, h0, l0); split2(x2, x3, h1, l1);
            uint32_t o0 = r0g * TPB + j0 * 2, o1 = (r0g + 8) * TPB + j0 * 2;
            *(uint32_t*)(smb + AH_O + o0) = h0; *(uint32_t*)(smb + AL_O + o0) = l0;
            *(uint32_t*)(smb + AH_O + o1) = h1; *(uint32_t*)(smb + AL_O + o1) = l1;
        }
        rs0 += __shfl_xor_sync(0xffffffffu, rs0, 1); rs0 += __shfl_xor_sync(0xffffffffu, rs0, 2);
        rs1 += __shfl_xor_sync(0xffffffffu, rs1, 1); rs1 += __shfl_xor_sync(0xffffffffu, rs1, 2);
        if ((lane & 3) == 0) {
            atomicAdd(&den_s[r0g], rs0);
            atomicAdd(&den_s[r0g + 8], rs1);
        }
    }
    __syncthreads();

    // ---- GEMM2: num = A V + Q S (3 split passes each) ----
    float cO[4][4];
    #pragma unroll
    for (int nt = 0; nt < 4; nt++) { cO[nt][0]=0; cO[nt][1]=0; cO[nt][2]=0; cO[nt][3]=0; }
    {
        const int dA[3] = {0, AL_O - AH_O, 0};
        const int dB[3] = {0, 0, VL_O - VH_O};
        #pragma unroll
        for (int p = 0; p < 3; p++) {
            uint32_t aB = aRowA + dA[p], bB = bRowV + dB[p];
            #pragma unroll
            for (int k0 = 0; k0 < 64; k0 += 16) {
                uint32_t a[4], b0,b1,b2,b3,b4,b5,b6,b7;
                ldsm4(aB + k0*2, a[0], a[1], a[2], a[3]);
                ldsm4t(bB + k0*TPB, b0, b1, b2, b3);
                ldsm4t(bB + k0*TPB + 32, b4, b5, b6, b7);
                mma16816(cO[0], a, b0, b1);
                mma16816(cO[1], a, b2, b3);
                mma16816(cO[2], a, b4, b5);
                mma16816(cO[3], a, b6, b7);
            }
        }
    }
    {
        const int dA[3] = {0, QL_O - QH_O, 0};
        const int dB[3] = {0, 0, SL_O - SH_O};
        #pragma unroll
        for (int p = 0; p < 3; p++) {
            uint32_t aB = aRowQ + dA[p], bB = bRowS + dB[p];
            #pragma unroll
            for (int k0 = 0; k0 < 128; k0 += 16) {
                uint32_t a[4], b0,b1,b2,b3,b4,b5,b6,b7;
                ldsm4(aB + k0*2, a[0], a[1], a[2], a[3]);
                ldsm4t(bB + k0*TPB, b0, b1, b2, b3);
                ldsm4t(bB + k0*TPB + 32, b4, b5, b6, b7);
                mma16816(cO[0], a, b0, b1);
                mma16816(cO[1], a, b2, b3);
                mma16816(cO[2], a, b4, b5);
                mma16816(cO[3], a, b6, b7);
            }
        }
    }

    // ---- normalize + store ----
    {
        int r0g = i0 + (lane >> 2);
        int cb  = n0 + 2 * (lane & 3);
        float inv0 = __fdividef(1.f, den_s[r0g]);
        float inv1 = __fdividef(1.f, den_s[r0g + 8]);
        float* orow0 = outg + (((size_t)b * Lc + c*64 + r0g    ) * Hc + h) * Dc;
        float* orow1 = outg + (((size_t)b * Lc + c*64 + r0g + 8) * Hc + h) * Dc;
        #pragma unroll
        for (int nt = 0; nt < 4; nt++) {
            int j0 = cb + 8 * nt;
            *(float2*)(orow0 + j0) = make_float2(cO[nt][0] * inv0, cO[nt][1] * inv0);
            *(float2*)(orow1 + j0) = make_float2(cO[nt][2] * inv1, cO[nt][3] * inv1);
        }
    }
}

// ---------------------------------------------------------------------------
extern "C" void kernel_launch(void* const* d_in, const int* in_sizes, int n_in,
                              void* d_out, int out_size)
{
    const float* q    = (const float*)d_in[0];
    const float* k    = (const float*)d_in[1];
    const float* v    = (const float*)d_in[2];
    const float* proj = (const float*)d_in[3];
    float* out = (float*)d_out;

    cudaFuncSetAttribute(proj_kernel,  cudaFuncAttributeMaxDynamicSharedMemorySize, PJ_SMEM * (int)sizeof(float));
    cudaFuncSetAttribute(chunk_kernel, cudaFuncAttributeMaxDynamicSharedMemorySize, CK_SMEM * (int)sizeof(float));
    cudaFuncSetAttribute(out_kernel,   cudaFuncAttributeMaxDynamicSharedMemorySize, OUT_SMEM);

    proj_kernel<<<2048, 256, PJ_SMEM * (int)sizeof(float)>>>(q, k, proj);
    chunk_kernel<<<BH * NCH, 256, CK_SMEM * (int)sizeof(float)>>>(v);
    prefix_kernel<<<BH * 32, 256>>>();
    out_kernel<<<BH * NCH, 256, OUT_SMEM>>>(v, out);
}

// round 10
// speedup vs baseline: 1.5794x; 1.5794x over previous
#include <cuda_runtime.h>
#include <cuda_bf16.h>
#include <cstdint>

#define Bc 2
#define Lc 4096
#define Hc 8
#define Dc 64
#define Mc 128
#define BH 16
#define NCH 64

typedef unsigned long long ull;

// ---- f32x2 helpers (proj/chunk SIMT kernels) ----
__device__ __forceinline__ ull pack2(float a, float b) {
    ull r; asm("mov.b64 %0, {%1, %2};" : "=l"(r) : "r"(__float_as_uint(a)), "r"(__float_as_uint(b))); return r;
}
__device__ __forceinline__ ull bcast2(float a) { return pack2(a, a); }
__device__ __forceinline__ void unpack2(ull v, float& a, float& b) {
    unsigned x, y; asm("mov.b64 {%0, %1}, %2;" : "=r"(x), "=r"(y) : "l"(v));
    a = __uint_as_float(x); b = __uint_as_float(y);
}
__device__ __forceinline__ void ffma2(ull& acc, ull a, ull b) {
    asm("fma.rn.f32x2 %0, %1, %2, %0;" : "+l"(acc) : "l"(a), "l"(b));
}

// ---- scratch ----
__device__ float g_qp[BH * Lc * Mc];            // [bh][chunk][r64][m128]
__device__ float g_kp[BH * Lc * Mc];            // [bh][chunk][c64][m128]
__device__ float g_state[BH * NCH * Dc * Mc];   // per chunk [m128][d64]
__device__ float g_ksum[BH * NCH * Mc];

// ---- warp-mma helpers ----
__device__ __forceinline__ uint32_t smem_u32(const void* p) {
    uint32_t a; asm("{ .reg .u64 t; cvta.to.shared.u64 t, %1; cvt.u32.u64 %0, t; }" : "=r"(a) : "l"(p)); return a;
}
__device__ __forceinline__ void ldsm4(uint32_t addr, uint32_t& r0, uint32_t& r1, uint32_t& r2, uint32_t& r3) {
    asm volatile("ldmatrix.sync.aligned.m8n8.x4.shared.b16 {%0,%1,%2,%3}, [%4];"
        : "=r"(r0), "=r"(r1), "=r"(r2), "=r"(r3) : "r"(addr));
}
__device__ __forceinline__ void ldsm4t(uint32_t addr, uint32_t& r0, uint32_t& r1, uint32_t& r2, uint32_t& r3) {
    asm volatile("ldmatrix.sync.aligned.m8n8.x4.trans.shared.b16 {%0,%1,%2,%3}, [%4];"
        : "=r"(r0), "=r"(r1), "=r"(r2), "=r"(r3) : "r"(addr));
}
__device__ __forceinline__ void mma16816(float* c, const uint32_t* a, uint32_t b0, uint32_t b1) {
    asm volatile("mma.sync.aligned.m16n8k16.row.col.f32.bf16.bf16.f32 "
        "{%0,%1,%2,%3}, {%4,%5,%6,%7}, {%8,%9}, {%0,%1,%2,%3};"
        : "+f"(c[0]), "+f"(c[1]), "+f"(c[2]), "+f"(c[3])
        : "r"(a[0]), "r"(a[1]), "r"(a[2]), "r"(a[3]), "r"(b0), "r"(b1));
}
__device__ __forceinline__ void split2(float a, float b, uint32_t& h, uint32_t& l) {
    __nv_bfloat162 hv = __floats2bfloat162_rn(a, b);
    float ra = a - __bfloat162float(__low2bfloat16(hv));
    float rb = b - __bfloat162float(__high2bfloat16(hv));
    __nv_bfloat162 lv = __floats2bfloat162_rn(ra, rb);
    h = *(uint32_t*)&hv; l = *(uint32_t*)&lv;
}

// ---------------------------------------------------------------------------
// Kernel 1: projection.  grid 2048: qk*1024 + bh*64 + chunk. Out: [r][m] tiles.
// ---------------------------------------------------------------------------
#define PJ_PT 132
#define PJ_RT 68
#define PJ_SMEM (64*PJ_PT + 64*PJ_RT)
__global__ void __launch_bounds__(256, 2)
proj_kernel(const float* __restrict__ qg, const float* __restrict__ kg, const float* __restrict__ pg)
{
    extern __shared__ float psm[];
    float* p_T    = psm;
    float* rows_T = psm + 64 * PJ_PT;
    int bid = blockIdx.x, qk = bid >> 10, bh = (bid >> 6) & 15, ck = bid & 63;
    int b = bh >> 3, h = bh & 7;
    const float* inp = qk ? kg : qg;
    float* outp = (qk ? g_kp : g_qp) + ((size_t)bh * Lc + ck * 64) * Mc;
    int tid = threadIdx.x;

    const float4* p4 = (const float4*)pg;
    float4 pbuf[8];
    #pragma unroll
    for (int k2 = 0; k2 < 8; k2++) pbuf[k2] = p4[tid + k2 * 256];
    float4 rbuf[4];
    #pragma unroll
    for (int k2 = 0; k2 < 4; k2++) {
        int t = tid + k2 * 256;
        int r = t >> 4;
        const float4* src = (const float4*)(inp + (((size_t)b * Lc + ck*64 + r) * Hc + h) * Dc);
        rbuf[k2] = src[t & 15];
    }
    #pragma unroll
    for (int k2 = 0; k2 < 8; k2++) {
        int t = tid + k2 * 256;
        int m = t >> 4, d0 = (t & 15) * 4;
        p_T[(d0+0)*PJ_PT + m] = pbuf[k2].x; p_T[(d0+1)*PJ_PT + m] = pbuf[k2].y;
        p_T[(d0+2)*PJ_PT + m] = pbuf[k2].z; p_T[(d0+3)*PJ_PT + m] = pbuf[k2].w;
    }
    #pragma unroll
    for (int k2 = 0; k2 < 4; k2++) {
        int t = tid + k2 * 256;
        int r = t >> 4, d0 = (t & 15) * 4;
        rows_T[(d0+0)*PJ_RT + r] = rbuf[k2].x; rows_T[(d0+1)*PJ_RT + r] = rbuf[k2].y;
        rows_T[(d0+2)*PJ_RT + r] = rbuf[k2].z; rows_T[(d0+3)*PJ_RT + r] = rbuf[k2].w;
    }
    __syncthreads();

    int mg = tid & 31, rg = tid >> 5;
    int m0 = 4 * mg, r0 = 8 * rg;
    ull acc2[4][4];
    #pragma unroll
    for (int a = 0; a < 4; a++) { acc2[a][0]=0; acc2[a][1]=0; acc2[a][2]=0; acc2[a][3]=0; }
    #pragma unroll 4
    for (int d = 0; d < 64; d++) {
        float4 pv  = *(const float4*)&p_T[d * PJ_PT + m0];
        float4 rv0 = *(const float4*)&rows_T[d * PJ_RT + r0];
        float4 rv1 = *(const float4*)&rows_T[d * PJ_RT + r0 + 4];
        ull rp[4] = { pack2(rv0.x,rv0.y), pack2(rv0.z,rv0.w), pack2(rv1.x,rv1.y), pack2(rv1.z,rv1.w) };
        ull pb[4] = { bcast2(pv.x), bcast2(pv.y), bcast2(pv.z), bcast2(pv.w) };
        #pragma unroll
        for (int a = 0; a < 4; a++)
            #pragma unroll
            for (int c = 0; c < 4; c++) ffma2(acc2[a][c], rp[a], pb[c]);
    }
    const float ratio = 0.08838834764831845f;
    #pragma unroll
    for (int a = 0; a < 4; a++) {
        float lo[4], hi[4];
        #pragma unroll
        for (int c = 0; c < 4; c++) {
            unpack2(acc2[a][c], lo[c], hi[c]);
            lo[c] *= ratio; lo[c] = (lo[c] > 0.f ? lo[c] : 0.f) + 1e-3f;
            hi[c] *= ratio; hi[c] = (hi[c] > 0.f ? hi[c] : 0.f) + 1e-3f;
        }
        *(float4*)&outp[(r0 + 2*a    ) * Mc + m0] = make_float4(lo[0], lo[1], lo[2], lo[3]);
        *(float4*)&outp[(r0 + 2*a + 1) * Mc + m0] = make_float4(hi[0], hi[1], hi[2], hi[3]);
    }
}

// ---------------------------------------------------------------------------
// Kernel 2: S[m][d] = sum_c K[c][m] V[c][d], z[m].  K tiles [c][m].
// ---------------------------------------------------------------------------
#define CK_KP 132
#define CK_VP 68
#define CK_SMEM (64*CK_KP + 64*CK_VP)
__global__ void __launch_bounds__(256, 2)
chunk_kernel(const float* __restrict__ vg)
{
    extern __shared__ float csm[];
    float* k_s = csm;
    float* v_s = csm + 64 * CK_KP;
    int tid = threadIdx.x, bh = blockIdx.x >> 6, c = blockIdx.x & 63;
    int b = bh >> 3, h = bh & 7;

    const float4* ksrc = (const float4*)&g_kp[((size_t)bh * Lc + c * 64) * Mc];
    float4 kbuf[8];
    #pragma unroll
    for (int k2 = 0; k2 < 8; k2++) kbuf[k2] = ksrc[tid + k2 * 256];
    float4 vbuf[4];
    #pragma unroll
    for (int k2 = 0; k2 < 4; k2++) {
        int t = tid + k2 * 256;
        int row = t >> 4;
        const float4* src = (const float4*)(vg + (((size_t)b * Lc + c*64 + row) * Hc + h) * Dc);
        vbuf[k2] = src[t & 15];
    }
    #pragma unroll
    for (int k2 = 0; k2 < 8; k2++) {
        int t = tid + k2 * 256;
        int cc = t >> 5, m0 = (t & 31) * 4;
        *(float4*)&k_s[cc * CK_KP + m0] = kbuf[k2];
    }
    #pragma unroll
    for (int k2 = 0; k2 < 4; k2++) {
        int t = tid + k2 * 256;
        int row = t >> 4, col = t & 15;
        *(float4*)&v_s[row * CK_VP + col * 4] = vbuf[k2];
    }
    __syncthreads();

    int mg = tid & 31, dg = tid >> 5;
    int d0 = dg * 8;
    ull acc2[4][4];
    #pragma unroll
    for (int i = 0; i < 4; i++) { acc2[i][0]=0; acc2[i][1]=0; acc2[i][2]=0; acc2[i][3]=0; }
    #pragma unroll 4
    for (int cc = 0; cc < 64; cc++) {
        ulonglong2 va = *(const ulonglong2*)&v_s[cc * CK_VP + d0];
        ulonglong2 vb = *(const ulonglong2*)&v_s[cc * CK_VP + d0 + 4];
        #pragma unroll
        for (int i = 0; i < 4; i++) {
            ull kb = bcast2(k_s[cc * CK_KP + mg + 32 * i]);
            ffma2(acc2[i][0], kb, va.x); ffma2(acc2[i][1], kb, va.y);
            ffma2(acc2[i][2], kb, vb.x); ffma2(acc2[i][3], kb, vb.y);
        }
    }
    float* Sp = &g_state[(size_t)blockIdx.x * (Dc * Mc)];
    #pragma unroll
    for (int i = 0; i < 4; i++) {
        int m = mg + 32 * i;
        float f0,f1,f2,f3,f4,f5,f6,f7;
        unpack2(acc2[i][0],f0,f1); unpack2(acc2[i][1],f2,f3);
        unpack2(acc2[i][2],f4,f5); unpack2(acc2[i][3],f6,f7);
        *(float4*)&Sp[m * 64 + d0]     = make_float4(f0,f1,f2,f3);
        *(float4*)&Sp[m * 64 + d0 + 4] = make_float4(f4,f5,f6,f7);
    }
    if (tid < 128) {
        float z = 0.f;
        #pragma unroll 8
        for (int cc = 0; cc < 64; cc++) z += k_s[cc * CK_KP + tid];
        g_ksum[(size_t)blockIdx.x * Mc + tid] = z;
    }
}

// ---------------------------------------------------------------------------
// Kernel 3: exclusive prefix over chunks (in place).
// ---------------------------------------------------------------------------
__global__ void prefix_kernel()
{
    int bh = blockIdx.x >> 5, slice = blockIdx.x & 31;
    int e = slice * 256 + threadIdx.x;
    size_t base = (size_t)bh * NCH * (Dc * Mc) + e;
    float acc = 0.f;
    #pragma unroll 1
    for (int c0 = 0; c0 < 64; c0 += 8) {
        float v[8];
        #pragma unroll
        for (int u = 0; u < 8; u++) v[u] = g_state[base + (size_t)(c0 + u) * (Dc * Mc)];
        #pragma unroll
        for (int u = 0; u < 8; u++) { g_state[base + (size_t)(c0 + u) * (Dc * Mc)] = acc; acc += v[u]; }
    }
    if (slice == 0 && threadIdx.x < 128) {
        size_t kb = (size_t)bh * NCH * Mc + threadIdx.x;
        float a2 = 0.f;
        #pragma unroll 1
        for (int c = 0; c < 64; c++) { float t = g_ksum[kb + (size_t)c * Mc]; g_ksum[kb + (size_t)c * Mc] = a2; a2 += t; }
    }
}

// ---------------------------------------------------------------------------
// Kernel 4: warp-MMA bf16-split out_kernel.  grid 1024, 256 threads (8 warps).
// ---------------------------------------------------------------------------
#define QPB 272
#define TPB 144
#define QH_O 0
#define QL_O 17408
#define KH_O 34816
#define KL_O 52224
#define SH_O 69632
#define SL_O 88064
#define VH_O 106496
#define VL_O 115712
#define AH_O 124928
#define AL_O 134144
#define KS_O 143360
#define DEN_O 143872
#define OUT_SMEM 144128

__global__ void __launch_bounds__(256, 1)
out_kernel(const float* __restrict__ vg, float* __restrict__ outg)
{
    extern __shared__ __align__(128) char smb[];
    uint32_t sb = smem_u32(smb);
    float* ks_s  = (float*)(smb + KS_O);
    float* den_s = (float*)(smb + DEN_O);

    int tid = threadIdx.x, lane = tid & 31, wid = tid >> 5;
    int bh = blockIdx.x >> 6, c = blockIdx.x & 63;
    int b = bh >> 3, h = bh & 7;

    const float* qt = g_qp + (size_t)blockIdx.x * (64 * Mc);
    const float* kt = g_kp + (size_t)blockIdx.x * (64 * Mc);
    const float* st = g_state + (size_t)blockIdx.x * (Mc * Dc);

    // ---- batched prefetch: issue all LDGs, then convert+store ----
    if (tid < 128) ks_s[tid] = g_ksum[(size_t)blockIdx.x * Mc + tid];

    float2 qbuf[16], kbuf[16];
    #pragma unroll
    for (int k2 = 0; k2 < 16; k2++) {
        int t = tid + k2 * 256;
        int r = t >> 6, m2 = (t & 63) * 2;
        qbuf[k2] = *(const float2*)(qt + r * Mc + m2);
        kbuf[k2] = *(const float2*)(kt + r * Mc + m2);
    }
    #pragma unroll
    for (int k2 = 0; k2 < 16; k2++) {
        int t = tid + k2 * 256;
        int r = t >> 6, m2 = (t & 63) * 2;
        uint32_t hq, lq, hk, lk;
        split2(qbuf[k2].x, qbuf[k2].y, hq, lq);
        split2(kbuf[k2].x, kbuf[k2].y, hk, lk);
        uint32_t off = r * QPB + m2 * 2;
        *(uint32_t*)(smb + QH_O + off) = hq; *(uint32_t*)(smb + QL_O + off) = lq;
        *(uint32_t*)(smb + KH_O + off) = hk; *(uint32_t*)(smb + KL_O + off) = lk;
    }
    {
        float2 sbuf[16];
        #pragma unroll
        for (int k2 = 0; k2 < 16; k2++) {
            int t = tid + k2 * 256;
            sbuf[k2] = *(const float2*)(st + (t >> 5) * Dc + (t & 31) * 2);
        }
        #pragma unroll
        for (int k2 = 0; k2 < 16; k2++) {
            int t = tid + k2 * 256;
            int m = t >> 5, d2 = (t & 31) * 2;
            uint32_t hs, ls; split2(sbuf[k2].x, sbuf[k2].y, hs, ls);
            uint32_t off = m * TPB + d2 * 2;
            *(uint32_t*)(smb + SH_O + off) = hs; *(uint32_t*)(smb + SL_O + off) = ls;
        }
    }
    {
        float2 vbuf[8];
        #pragma unroll
        for (int k2 = 0; k2 < 8; k2++) {
            int t = tid + k2 * 256;
            int j = t >> 5, d2 = (t & 31) * 2;
            vbuf[k2] = *(const float2*)(vg + (((size_t)b * Lc + c*64 + j) * Hc + h) * Dc + d2);
        }
        #pragma unroll
        for (int k2 = 0; k2 < 8; k2++) {
            int t = tid + k2 * 256;
            int j = t >> 5, d2 = (t & 31) * 2;
            uint32_t hv, lv; split2(vbuf[k2].x, vbuf[k2].y, hv, lv);
            uint32_t off = j * TPB + d2 * 2;
            *(uint32_t*)(smb + VH_O + off) = hv; *(uint32_t*)(smb + VL_O + off) = lv;
        }
    }
    __syncthreads();

    // den init: Q . ksum (fully unrolled, high MLP)
    if (tid < 64) {
        const float4* qr = (const float4*)(qt + tid * Mc);
        float qd = 0.f;
        #pragma unroll
        for (int m4 = 0; m4 < 32; m4++) {
            float4 q4 = qr[m4];
            qd += q4.x * ks_s[4*m4] + q4.y * ks_s[4*m4+1] + q4.z * ks_s[4*m4+2] + q4.w * ks_s[4*m4+3];
        }
        den_s[tid] = qd;
    }
    // REQUIRED: den init must happen-before the atomicAdd rowsum accumulation
    // below (for chunk 0, ksum==0, so den comes entirely from the atomics —
    // a racing init store would zero it -> 1/0 = inf).
    __syncthreads();

    int rw = wid & 3, cw = wid >> 2;
    int i0 = 16 * rw, n0 = 32 * cw;
    int q4i = lane >> 3, rr = lane & 7;

    uint32_t aRowQ = sb + QH_O + (i0 + (lane & 15)) * QPB + (lane >> 4) * 16;
    uint32_t bRowK = sb + KH_O + (n0 + 8 * (q4i >> 1) + rr) * QPB + (q4i & 1) * 16;
    uint32_t aRowA = sb + AH_O + (i0 + (lane & 15)) * TPB + (lane >> 4) * 16;
    uint32_t bRowV = sb + VH_O + (8 * (q4i & 1) + rr) * TPB + (n0 + 8 * (q4i >> 1)) * 2;
    uint32_t bRowS = sb + SH_O + (8 * (q4i & 1) + rr) * TPB + (n0 + 8 * (q4i >> 1)) * 2;

    // ---- GEMM1: A = Q K^T, operands loaded once per k-step ----
    float cA[4][4];
    #pragma unroll
    for (int nt = 0; nt < 4; nt++) { cA[nt][0]=0; cA[nt][1]=0; cA[nt][2]=0; cA[nt][3]=0; }
    #pragma unroll
    for (int k0 = 0; k0 < 128; k0 += 16) {
        uint32_t aH[4], aL[4], bHa[4], bHb[4], bLa[4], bLb[4];
        ldsm4(aRowQ + k0*2,                   aH[0], aH[1], aH[2], aH[3]);
        ldsm4(aRowQ + (QL_O-QH_O) + k0*2,     aL[0], aL[1], aL[2], aL[3]);
        ldsm4(bRowK + k0*2,                   bHa[0], bHa[1], bHa[2], bHa[3]);
        ldsm4(bRowK + 16*QPB + k0*2,          bHb[0], bHb[1], bHb[2], bHb[3]);
        ldsm4(bRowK + (KL_O-KH_O) + k0*2,         bLa[0], bLa[1], bLa[2], bLa[3]);
        ldsm4(bRowK + (KL_O-KH_O) + 16*QPB + k0*2, bLb[0], bLb[1], bLb[2], bLb[3]);
        mma16816(cA[0], aH, bHa[0], bHa[1]); mma16816(cA[1], aH, bHa[2], bHa[3]);
        mma16816(cA[2], aH, bHb[0], bHb[1]); mma16816(cA[3], aH, bHb[2], bHb[3]);
        mma16816(cA[0], aH, bLa[0], bLa[1]); mma16816(cA[1], aH, bLa[2], bLa[3]);
        mma16816(cA[2], aH, bLb[0], bLb[1]); mma16816(cA[3], aH, bLb[2], bLb[3]);
        mma16816(cA[0], aL, bHa[0], bHa[1]); mma16816(cA[1], aL, bHa[2], bHa[3]);
        mma16816(cA[2], aL, bHb[0], bHb[1]); mma16816(cA[3], aL, bHb[2], bHb[3]);
    }

    // ---- mask, rowsum, split-store A ----
    {
        int r0g = i0 + (lane >> 2);
        int cb  = n0 + 2 * (lane & 3);
        float rs0 = 0.f, rs1 = 0.f;
        #pragma unroll
        for (int nt = 0; nt < 4; nt++) {
            int j0 = cb + 8 * nt;
            float x0 = (j0     <= r0g    ) ? cA[nt][0] : 0.f;
            float x1 = (j0 + 1 <= r0g    ) ? cA[nt][1] : 0.f;
            float x2 = (j0     <= r0g + 8) ? cA[nt][2] : 0.f;
            float x3 = (j0 + 1 <= r0g + 8) ? cA[nt][3] : 0.f;
            rs0 += x0 + x1; rs1 += x2 + x3;
            uint32_t h0, l0, h1, l1;
            split2(x0, x1, h0, l0); split2(x2, x3, h1, l1);
            uint32_t o0 = r0g * TPB + j0 * 2, o1 = (r0g + 8) * TPB + j0 * 2;
            *(uint32_t*)(smb + AH_O + o0) = h0; *(uint32_t*)(smb + AL_O + o0) = l0;
            *(uint32_t*)(smb + AH_O + o1) = h1; *(uint32_t*)(smb + AL_O + o1) = l1;
        }
        rs0 += __shfl_xor_sync(0xffffffffu, rs0, 1); rs0 += __shfl_xor_sync(0xffffffffu, rs0, 2);
        rs1 += __shfl_xor_sync(0xffffffffu, rs1, 1); rs1 += __shfl_xor_sync(0xffffffffu, rs1, 2);
        if ((lane & 3) == 0) {
            atomicAdd(&den_s[r0g], rs0);
            atomicAdd(&den_s[r0g + 8], rs1);
        }
    }
    __syncthreads();

    // ---- GEMM2: num = A V + Q S, operands loaded once per k-step ----
    float cO[4][4];
    #pragma unroll
    for (int nt = 0; nt < 4; nt++) { cO[nt][0]=0; cO[nt][1]=0; cO[nt][2]=0; cO[nt][3]=0; }
    #pragma unroll
    for (int k0 = 0; k0 < 64; k0 += 16) {        // A V
        uint32_t aH[4], aL[4], bHa[4], bHb[4], bLa[4], bLb[4];
        ldsm4(aRowA + k0*2,               aH[0], aH[1], aH[2], aH[3]);
        ldsm4(aRowA + (AL_O-AH_O) + k0*2, aL[0], aL[1], aL[2], aL[3]);
        ldsm4t(bRowV + k0*TPB,                  bHa[0], bHa[1], bHa[2], bHa[3]);
        ldsm4t(bRowV + k0*TPB + 32,             bHb[0], bHb[1], bHb[2], bHb[3]);
        ldsm4t(bRowV + (VL_O-VH_O) + k0*TPB,      bLa[0], bLa[1], bLa[2], bLa[3]);
        ldsm4t(bRowV + (VL_O-VH_O) + k0*TPB + 32, bLb[0], bLb[1], bLb[2], bLb[3]);
        mma16816(cO[0], aH, bHa[0], bHa[1]); mma16816(cO[1], aH, bHa[2], bHa[3]);
        mma16816(cO[2], aH, bHb[0], bHb[1]); mma16816(cO[3], aH, bHb[2], bHb[3]);
        mma16816(cO[0], aL, bHa[0], bHa[1]); mma16816(cO[1], aL, bHa[2], bHa[3]);
        mma16816(cO[2], aL, bHb[0], bHb[1]); mma16816(cO[3], aL, bHb[2], bHb[3]);
        mma16816(cO[0], aH, bLa[0], bLa[1]); mma16816(cO[1], aH, bLa[2], bLa[3]);
        mma16816(cO[2], aH, bLb[0], bLb[1]); mma16816(cO[3], aH, bLb[2], bLb[3]);
    }
    #pragma unroll
    for (int k0 = 0; k0 < 128; k0 += 16) {       // Q S
        uint32_t aH[4], aL[4], bHa[4], bHb[4], bLa[4], bLb[4];
        ldsm4(aRowQ + k0*2,               aH[0], aH[1], aH[2], aH[3]);
        ldsm4(aRowQ + (QL_O-QH_O) + k0*2, aL[0], aL[1], aL[2], aL[3]);
        ldsm4t(bRowS + k0*TPB,                  bHa[0], bHa[1], bHa[2], bHa[3]);
        ldsm4t(bRowS + k0*TPB + 32,             bHb[0], bHb[1], bHb[2], bHb[3]);
        ldsm4t(bRowS + (SL_O-SH_O) + k0*TPB,      bLa[0], bLa[1], bLa[2], bLa[3]);
        ldsm4t(bRowS + (SL_O-SH_O) + k0*TPB + 32, bLb[0], bLb[1], bLb[2], bLb[3]);
        mma16816(cO[0], aH, bHa[0], bHa[1]); mma16816(cO[1], aH, bHa[2], bHa[3]);
        mma16816(cO[2], aH, bHb[0], bHb[1]); mma16816(cO[3], aH, bHb[2], bHb[3]);
        mma16816(cO[0], aL, bHa[0], bHa[1]); mma16816(cO[1], aL, bHa[2], bHa[3]);
        mma16816(cO[2], aL, bHb[0], bHb[1]); mma16816(cO[3], aL, bHb[2], bHb[3]);
        mma16816(cO[0], aH, bLa[0], bLa[1]); mma16816(cO[1], aH, bLa[2], bLa[3]);
        mma16816(cO[2], aH, bLb[0], bLb[1]); mma16816(cO[3], aH, bLb[2], bLb[3]);
    }

    // ---- normalize + store ----
    {
        int r0g = i0 + (lane >> 2);
        int cb  = n0 + 2 * (lane & 3);
        float inv0 = __fdividef(1.f, den_s[r0g]);
        float inv1 = __fdividef(1.f, den_s[r0g + 8]);
        float* orow0 = outg + (((size_t)b * Lc + c*64 + r0g    ) * Hc + h) * Dc;
        float* orow1 = outg + (((size_t)b * Lc + c*64 + r0g + 8) * Hc + h) * Dc;
        #pragma unroll
        for (int nt = 0; nt < 4; nt++) {
            int j0 = cb + 8 * nt;
            *(float2*)(orow0 + j0) = make_float2(cO[nt][0] * inv0, cO[nt][1] * inv0);
            *(float2*)(orow1 + j0) = make_float2(cO[nt][2] * inv1, cO[nt][3] * inv1);
        }
    }
}

// ---------------------------------------------------------------------------
extern "C" void kernel_launch(void* const* d_in, const int* in_sizes, int n_in,
                              void* d_out, int out_size)
{
    const float* q    = (const float*)d_in[0];
    const float* k    = (const float*)d_in[1];
    const float* v    = (const float*)d_in[2];
    const float* proj = (const float*)d_in[3];
    float* out = (float*)d_out;

    cudaFuncSetAttribute(proj_kernel,  cudaFuncAttributeMaxDynamicSharedMemorySize, PJ_SMEM * (int)sizeof(float));
    cudaFuncSetAttribute(chunk_kernel, cudaFuncAttributeMaxDynamicSharedMemorySize, CK_SMEM * (int)sizeof(float));
    cudaFuncSetAttribute(out_kernel,   cudaFuncAttributeMaxDynamicSharedMemorySize, OUT_SMEM);

    proj_kernel<<<2048, 256, PJ_SMEM * (int)sizeof(float)>>>(q, k, proj);
    chunk_kernel<<<BH * NCH, 256, CK_SMEM * (int)sizeof(float)>>>(v);
    prefix_kernel<<<BH * 32, 256>>>();
    out_kernel<<<BH * NCH, 256, OUT_SMEM>>>(v, out);
}

// round 11
// speedup vs baseline: 2.1363x; 1.3526x over previous
#include <cuda_runtime.h>
#include <cuda_bf16.h>
#include <cstdint>

#define Bc 2
#define Lc 4096
#define Hc 8
#define Dc 64
#define Mc 128
#define BH 16
#define NCH 64

typedef unsigned long long ull;

// ---- scratch ----
__device__ float g_qp[BH * Lc * Mc];            // [bh][chunk][r64][m128]
__device__ float g_kp[BH * Lc * Mc];            // [bh][chunk][c64][m128]
__device__ float g_state[BH * NCH * Dc * Mc];   // per chunk [m128][d64]
__device__ float g_ksum[BH * NCH * Mc];

// ---- warp-mma helpers ----
__device__ __forceinline__ uint32_t smem_u32(const void* p) {
    uint32_t a; asm("{ .reg .u64 t; cvta.to.shared.u64 t, %1; cvt.u32.u64 %0, t; }" : "=r"(a) : "l"(p)); return a;
}
__device__ __forceinline__ void ldsm4(uint32_t addr, uint32_t& r0, uint32_t& r1, uint32_t& r2, uint32_t& r3) {
    asm volatile("ldmatrix.sync.aligned.m8n8.x4.shared.b16 {%0,%1,%2,%3}, [%4];"
        : "=r"(r0), "=r"(r1), "=r"(r2), "=r"(r3) : "r"(addr));
}
__device__ __forceinline__ void ldsm4t(uint32_t addr, uint32_t& r0, uint32_t& r1, uint32_t& r2, uint32_t& r3) {
    asm volatile("ldmatrix.sync.aligned.m8n8.x4.trans.shared.b16 {%0,%1,%2,%3}, [%4];"
        : "=r"(r0), "=r"(r1), "=r"(r2), "=r"(r3) : "r"(addr));
}
__device__ __forceinline__ void mma16816(float* c, const uint32_t* a, uint32_t b0, uint32_t b1) {
    asm volatile("mma.sync.aligned.m16n8k16.row.col.f32.bf16.bf16.f32 "
        "{%0,%1,%2,%3}, {%4,%5,%6,%7}, {%8,%9}, {%0,%1,%2,%3};"
        : "+f"(c[0]), "+f"(c[1]), "+f"(c[2]), "+f"(c[3])
        : "r"(a[0]), "r"(a[1]), "r"(a[2]), "r"(a[3]), "r"(b0), "r"(b1));
}
__device__ __forceinline__ void split2(float a, float b, uint32_t& h, uint32_t& l) {
    __nv_bfloat162 hv = __floats2bfloat162_rn(a, b);
    float ra = a - __bfloat162float(__low2bfloat16(hv));
    float rb = b - __bfloat162float(__high2bfloat16(hv));
    __nv_bfloat162 lv = __floats2bfloat162_rn(ra, rb);
    h = *(uint32_t*)&hv; l = *(uint32_t*)&lv;
}

// ---------------------------------------------------------------------------
// Kernel 1: projection via HMMA bf16-split.
// grid 2048: qk*1024 + bh*64 + chunk.  out[r][m] = relu(ratio * data . P^T) + eps
// M=64 rows, N=128 (m), K=64 (d).  8 warps: 4 row-groups x 2 col-halves.
// ---------------------------------------------------------------------------
#define PTB 144      // byte pitch for 64-col bf16 tiles
#define PDH_O 0
#define PDL_O 9216
#define PPH_O 18432
#define PPL_O 36864
#define PJ_SMEM 55296

__global__ void __launch_bounds__(256, 2)
proj_kernel(const float* __restrict__ qg, const float* __restrict__ kg, const float* __restrict__ pg)
{
    extern __shared__ __align__(128) char smb[];
    uint32_t sb = smem_u32(smb);
    int tid = threadIdx.x, lane = tid & 31, wid = tid >> 5;
    int bid = blockIdx.x, qk = bid >> 10, bh = (bid >> 6) & 15, ck = bid & 63;
    int b = bh >> 3, h = bh & 7;
    const float* inp = qk ? kg : qg;
    float* outp = (qk ? g_kp : g_qp) + ((size_t)bh * Lc + ck * 64) * Mc;

    // batched prefetch
    const float4* p4 = (const float4*)pg;
    float4 pbuf[8];
    #pragma unroll
    for (int k2 = 0; k2 < 8; k2++) pbuf[k2] = p4[tid + k2 * 256];
    float4 rbuf[4];
    #pragma unroll
    for (int k2 = 0; k2 < 4; k2++) {
        int t = tid + k2 * 256;
        int r = t >> 4;
        const float4* src = (const float4*)(inp + (((size_t)b * Lc + ck*64 + r) * Hc + h) * Dc);
        rbuf[k2] = src[t & 15];
    }
    // split+store: P [m][d] -> PH/PL
    #pragma unroll
    for (int k2 = 0; k2 < 8; k2++) {
        int t = tid + k2 * 256;
        int m = t >> 4, d0 = (t & 15) * 4;
        uint32_t h0, l0, h1, l1;
        split2(pbuf[k2].x, pbuf[k2].y, h0, l0);
        split2(pbuf[k2].z, pbuf[k2].w, h1, l1);
        uint32_t off = m * PTB + d0 * 2;
        *(uint32_t*)(smb + PPH_O + off) = h0; *(uint32_t*)(smb + PPH_O + off + 4) = h1;
        *(uint32_t*)(smb + PPL_O + off) = l0; *(uint32_t*)(smb + PPL_O + off + 4) = l1;
    }
    // data [r][d] -> DH/DL
    #pragma unroll
    for (int k2 = 0; k2 < 4; k2++) {
        int t = tid + k2 * 256;
        int r = t >> 4, d0 = (t & 15) * 4;
        uint32_t h0, l0, h1, l1;
        split2(rbuf[k2].x, rbuf[k2].y, h0, l0);
        split2(rbuf[k2].z, rbuf[k2].w, h1, l1);
        uint32_t off = r * PTB + d0 * 2;
        *(uint32_t*)(smb + PDH_O + off) = h0; *(uint32_t*)(smb + PDH_O + off + 4) = h1;
        *(uint32_t*)(smb + PDL_O + off) = l0; *(uint32_t*)(smb + PDL_O + off + 4) = l1;
    }
    __syncthreads();

    int rw = wid & 3, cw = wid >> 2;       // cw in 0..1
    int i0 = 16 * rw, n0 = 64 * cw;
    int q4i = lane >> 3, rr = lane & 7;
    uint32_t aRow = sb + PDH_O + (i0 + (lane & 15)) * PTB + (lane >> 4) * 16;
    uint32_t bRow = sb + PPH_O + (n0 + 8 * (q4i >> 1) + rr) * PTB + (q4i & 1) * 16;

    float cO[8][4];
    #pragma unroll
    for (int t8 = 0; t8 < 8; t8++) { cO[t8][0]=0; cO[t8][1]=0; cO[t8][2]=0; cO[t8][3]=0; }

    #pragma unroll
    for (int k0 = 0; k0 < 64; k0 += 16) {
        uint32_t aH[4], aL[4];
        ldsm4(aRow + k0*2,                 aH[0], aH[1], aH[2], aH[3]);
        ldsm4(aRow + (PDL_O-PDH_O) + k0*2, aL[0], aL[1], aL[2], aL[3]);
        uint32_t bH[4][4], bL[4][4];
        #pragma unroll
        for (int nt = 0; nt < 4; nt++) {
            ldsm4(bRow + nt*16*PTB + k0*2,                 bH[nt][0], bH[nt][1], bH[nt][2], bH[nt][3]);
            ldsm4(bRow + (PPL_O-PPH_O) + nt*16*PTB + k0*2, bL[nt][0], bL[nt][1], bL[nt][2], bL[nt][3]);
        }
        #pragma unroll
        for (int nt = 0; nt < 4; nt++) {
            mma16816(cO[2*nt],   aH, bH[nt][0], bH[nt][1]);
            mma16816(cO[2*nt+1], aH, bH[nt][2], bH[nt][3]);
            mma16816(cO[2*nt],   aH, bL[nt][0], bL[nt][1]);
            mma16816(cO[2*nt+1], aH, bL[nt][2], bL[nt][3]);
            mma16816(cO[2*nt],   aL, bH[nt][0], bH[nt][1]);
            mma16816(cO[2*nt+1], aL, bH[nt][2], bH[nt][3]);
        }
    }

    const float ratio = 0.08838834764831845f;
    int r0g = i0 + (lane >> 2);
    int cb  = 2 * (lane & 3);
    #pragma unroll
    for (int t8 = 0; t8 < 8; t8++) {
        int j = n0 + cb + 8 * t8;
        float v0 = cO[t8][0]*ratio, v1 = cO[t8][1]*ratio, v2 = cO[t8][2]*ratio, v3 = cO[t8][3]*ratio;
        v0 = (v0 > 0.f ? v0 : 0.f) + 1e-3f; v1 = (v1 > 0.f ? v1 : 0.f) + 1e-3f;
        v2 = (v2 > 0.f ? v2 : 0.f) + 1e-3f; v3 = (v3 > 0.f ? v3 : 0.f) + 1e-3f;
        *(float2*)&outp[r0g * Mc + j]       = make_float2(v0, v1);
        *(float2*)&outp[(r0g + 8) * Mc + j] = make_float2(v2, v3);
    }
}

// ---------------------------------------------------------------------------
// Kernel 2: S[m][d] = K^T V via HMMA bf16-split.  M=128 (m), N=64 (d), K=64 (c).
// A = K^T from [c][m] tile via ldsm4t; B = V [c][d] via ldsm4t.
// 8 warps: one 16-row m-group each, full 64 d.  z[m] exact fp32.
// ---------------------------------------------------------------------------
#define KPB 272
#define VPB 144
#define CKH_O 0
#define CKL_O 17408
#define CVH_O 34816
#define CVL_O 44032
#define CK_SMEM 53248

__global__ void __launch_bounds__(256, 2)
chunk_kernel(const float* __restrict__ vg)
{
    extern __shared__ __align__(128) char smb[];
    uint32_t sb = smem_u32(smb);
    int tid = threadIdx.x, lane = tid & 31, wid = tid >> 5;
    int bh = blockIdx.x >> 6, c = blockIdx.x & 63;
    int b = bh >> 3, h = bh & 7;

    const float* kq = &g_kp[((size_t)bh * Lc + c * 64) * Mc];   // [c][m]
    const float4* ksrc = (const float4*)kq;

    float4 kbuf[8];
    #pragma unroll
    for (int k2 = 0; k2 < 8; k2++) kbuf[k2] = ksrc[tid + k2 * 256];
    float4 vbuf[4];
    #pragma unroll
    for (int k2 = 0; k2 < 4; k2++) {
        int t = tid + k2 * 256;
        int row = t >> 4;
        const float4* src = (const float4*)(vg + (((size_t)b * Lc + c*64 + row) * Hc + h) * Dc);
        vbuf[k2] = src[t & 15];
    }
    #pragma unroll
    for (int k2 = 0; k2 < 8; k2++) {
        int t = tid + k2 * 256;
        int cc = t >> 5, m0 = (t & 31) * 4;
        uint32_t h0, l0, h1, l1;
        split2(kbuf[k2].x, kbuf[k2].y, h0, l0);
        split2(kbuf[k2].z, kbuf[k2].w, h1, l1);
        uint32_t off = cc * KPB + m0 * 2;
        *(uint32_t*)(smb + CKH_O + off) = h0; *(uint32_t*)(smb + CKH_O + off + 4) = h1;
        *(uint32_t*)(smb + CKL_O + off) = l0; *(uint32_t*)(smb + CKL_O + off + 4) = l1;
    }
    #pragma unroll
    for (int k2 = 0; k2 < 4; k2++) {
        int t = tid + k2 * 256;
        int row = t >> 4, d0 = (t & 15) * 4;
        uint32_t h0, l0, h1, l1;
        split2(vbuf[k2].x, vbuf[k2].y, h0, l0);
        split2(vbuf[k2].z, vbuf[k2].w, h1, l1);
        uint32_t off = row * VPB + d0 * 2;
        *(uint32_t*)(smb + CVH_O + off) = h0; *(uint32_t*)(smb + CVH_O + off + 4) = h1;
        *(uint32_t*)(smb + CVL_O + off) = l0; *(uint32_t*)(smb + CVL_O + off + 4) = l1;
    }
    __syncthreads();

    int i0 = wid * 16;                       // m tile base
    int q4i = lane >> 3, rr = lane & 7;
    // A = K^T: trans load from [c][m]; a-frag order m0k0/m8k0/m0k8/m8k8
    uint32_t aRow = sb + CKH_O + (8 * (lane >> 4) + rr) * KPB + (i0 + 8 * (q4i & 1)) * 2;
    // B = V: trans load from [c][d]
    uint32_t bRow = sb + CVH_O + (8 * (q4i & 1) + rr) * VPB + (8 * (q4i >> 1)) * 2;

    float cS[8][4];
    #pragma unroll
    for (int t8 = 0; t8 < 8; t8++) { cS[t8][0]=0; cS[t8][1]=0; cS[t8][2]=0; cS[t8][3]=0; }

    #pragma unroll
    for (int c0 = 0; c0 < 64; c0 += 16) {
        uint32_t aH[4], aL[4];
        ldsm4t(aRow + c0*KPB,                 aH[0], aH[1], aH[2], aH[3]);
        ldsm4t(aRow + (CKL_O-CKH_O) + c0*KPB, aL[0], aL[1], aL[2], aL[3]);
        uint32_t bH[4][4], bL[4][4];
        #pragma unroll
        for (int nt = 0; nt < 4; nt++) {
            ldsm4t(bRow + c0*VPB + nt*32,                 bH[nt][0], bH[nt][1], bH[nt][2], bH[nt][3]);
            ldsm4t(bRow + (CVL_O-CVH_O) + c0*VPB + nt*32, bL[nt][0], bL[nt][1], bL[nt][2], bL[nt][3]);
        }
        #pragma unroll
        for (int nt = 0; nt < 4; nt++) {
            mma16816(cS[2*nt],   aH, bH[nt][0], bH[nt][1]);
            mma16816(cS[2*nt+1], aH, bH[nt][2], bH[nt][3]);
            mma16816(cS[2*nt],   aH, bL[nt][0], bL[nt][1]);
            mma16816(cS[2*nt+1], aH, bL[nt][2], bL[nt][3]);
            mma16816(cS[2*nt],   aL, bH[nt][0], bH[nt][1]);
            mma16816(cS[2*nt+1], aL, bH[nt][2], bH[nt][3]);
        }
    }

    float* Sp = &g_state[(size_t)blockIdx.x * (Dc * Mc)];
    int m0g = i0 + (lane >> 2);
    int cb  = 2 * (lane & 3);
    #pragma unroll
    for (int t8 = 0; t8 < 8; t8++) {
        int d = cb + 8 * t8;
        *(float2*)&Sp[m0g * 64 + d]       = make_float2(cS[t8][0], cS[t8][1]);
        *(float2*)&Sp[(m0g + 8) * 64 + d] = make_float2(cS[t8][2], cS[t8][3]);
    }

    // z[m] exact fp32 (column sums; K tile is hot in L2)
    if (tid < 128) {
        float z = 0.f;
        #pragma unroll
        for (int cc = 0; cc < 64; cc++) z += kq[cc * Mc + tid];
        g_ksum[(size_t)blockIdx.x * Mc + tid] = z;
    }
}

// ---------------------------------------------------------------------------
// Kernel 3: exclusive prefix over chunks (in place).
// ---------------------------------------------------------------------------
__global__ void prefix_kernel()
{
    int bh = blockIdx.x >> 5, slice = blockIdx.x & 31;
    int e = slice * 256 + threadIdx.x;
    size_t base = (size_t)bh * NCH * (Dc * Mc) + e;
    float acc = 0.f;
    #pragma unroll 1
    for (int c0 = 0; c0 < 64; c0 += 8) {
        float v[8];
        #pragma unroll
        for (int u = 0; u < 8; u++) v[u] = g_state[base + (size_t)(c0 + u) * (Dc * Mc)];
        #pragma unroll
        for (int u = 0; u < 8; u++) { g_state[base + (size_t)(c0 + u) * (Dc * Mc)] = acc; acc += v[u]; }
    }
    if (slice == 0 && threadIdx.x < 128) {
        size_t kb = (size_t)bh * NCH * Mc + threadIdx.x;
        float a2 = 0.f;
        #pragma unroll 1
        for (int c = 0; c < 64; c++) { float t = g_ksum[kb + (size_t)c * Mc]; g_ksum[kb + (size_t)c * Mc] = a2; a2 += t; }
    }
}

// ---------------------------------------------------------------------------
// Kernel 4: warp-MMA bf16-split out_kernel (unchanged from R10 winner).
// ---------------------------------------------------------------------------
#define QPB 272
#define TPB 144
#define QH_O 0
#define QL_O 17408
#define KH_O 34816
#define KL_O 52224
#define SH_O 69632
#define SL_O 88064
#define VH_O 106496
#define VL_O 115712
#define AH_O 124928
#define AL_O 134144
#define KS_O 143360
#define DEN_O 143872
#define OUT_SMEM 144128

__global__ void __launch_bounds__(256, 1)
out_kernel(const float* __restrict__ vg, float* __restrict__ outg)
{
    extern __shared__ __align__(128) char smb[];
    uint32_t sb = smem_u32(smb);
    float* ks_s  = (float*)(smb + KS_O);
    float* den_s = (float*)(smb + DEN_O);

    int tid = threadIdx.x, lane = tid & 31, wid = tid >> 5;
    int bh = blockIdx.x >> 6, c = blockIdx.x & 63;
    int b = bh >> 3, h = bh & 7;

    const float* qt = g_qp + (size_t)blockIdx.x * (64 * Mc);
    const float* kt = g_kp + (size_t)blockIdx.x * (64 * Mc);
    const float* st = g_state + (size_t)blockIdx.x * (Mc * Dc);

    if (tid < 128) ks_s[tid] = g_ksum[(size_t)blockIdx.x * Mc + tid];

    float2 qbuf[16], kbuf[16];
    #pragma unroll
    for (int k2 = 0; k2 < 16; k2++) {
        int t = tid + k2 * 256;
        int r = t >> 6, m2 = (t & 63) * 2;
        qbuf[k2] = *(const float2*)(qt + r * Mc + m2);
        kbuf[k2] = *(const float2*)(kt + r * Mc + m2);
    }
    #pragma unroll
    for (int k2 = 0; k2 < 16; k2++) {
        int t = tid + k2 * 256;
        int r = t >> 6, m2 = (t & 63) * 2;
        uint32_t hq, lq, hk, lk;
        split2(qbuf[k2].x, qbuf[k2].y, hq, lq);
        split2(kbuf[k2].x, kbuf[k2].y, hk, lk);
        uint32_t off = r * QPB + m2 * 2;
        *(uint32_t*)(smb + QH_O + off) = hq; *(uint32_t*)(smb + QL_O + off) = lq;
        *(uint32_t*)(smb + KH_O + off) = hk; *(uint32_t*)(smb + KL_O + off) = lk;
    }
    {
        float2 sbuf[16];
        #pragma unroll
        for (int k2 = 0; k2 < 16; k2++) {
            int t = tid + k2 * 256;
            sbuf[k2] = *(const float2*)(st + (t >> 5) * Dc + (t & 31) * 2);
        }
        #pragma unroll
        for (int k2 = 0; k2 < 16; k2++) {
            int t = tid + k2 * 256;
            int m = t >> 5, d2 = (t & 31) * 2;
            uint32_t hs, ls; split2(sbuf[k2].x, sbuf[k2].y, hs, ls);
            uint32_t off = m * TPB + d2 * 2;
            *(uint32_t*)(smb + SH_O + off) = hs; *(uint32_t*)(smb + SL_O + off) = ls;
        }
    }
    {
        float2 vbuf[8];
        #pragma unroll
        for (int k2 = 0; k2 < 8; k2++) {
            int t = tid + k2 * 256;
            int j = t >> 5, d2 = (t & 31) * 2;
            vbuf[k2] = *(const float2*)(vg + (((size_t)b * Lc + c*64 + j) * Hc + h) * Dc + d2);
        }
        #pragma unroll
        for (int k2 = 0; k2 < 8; k2++) {
            int t = tid + k2 * 256;
            int j = t >> 5, d2 = (t & 31) * 2;
            uint32_t hv, lv; split2(vbuf[k2].x, vbuf[k2].y, hv, lv);
            uint32_t off = j * TPB + d2 * 2;
            *(uint32_t*)(smb + VH_O + off) = hv; *(uint32_t*)(smb + VL_O + off) = lv;
        }
    }
    __syncthreads();

    if (tid < 64) {
        const float4* qr = (const float4*)(qt + tid * Mc);
        float qd = 0.f;
        #pragma unroll
        for (int m4 = 0; m4 < 32; m4++) {
            float4 q4 = qr[m4];
            qd += q4.x * ks_s[4*m4] + q4.y * ks_s[4*m4+1] + q4.z * ks_s[4*m4+2] + q4.w * ks_s[4*m4+3];
        }
        den_s[tid] = qd;
    }
    // den init must happen-before the atomicAdd rowsum accumulation below.
    __syncthreads();

    int rw = wid & 3, cw = wid >> 2;
    int i0 = 16 * rw, n0 = 32 * cw;
    int q4i = lane >> 3, rr = lane & 7;

    uint32_t aRowQ = sb + QH_O + (i0 + (lane & 15)) * QPB + (lane >> 4) * 16;
    uint32_t bRowK = sb + KH_O + (n0 + 8 * (q4i >> 1) + rr) * QPB + (q4i & 1) * 16;
    uint32_t aRowA = sb + AH_O + (i0 + (lane & 15)) * TPB + (lane >> 4) * 16;
    uint32_t bRowV = sb + VH_O + (8 * (q4i & 1) + rr) * TPB + (n0 + 8 * (q4i >> 1)) * 2;
    uint32_t bRowS = sb + SH_O + (8 * (q4i & 1) + rr) * TPB + (n0 + 8 * (q4i >> 1)) * 2;

    float cA[4][4];
    #pragma unroll
    for (int nt = 0; nt < 4; nt++) { cA[nt][0]=0; cA[nt][1]=0; cA[nt][2]=0; cA[nt][3]=0; }
    #pragma unroll
    for (int k0 = 0; k0 < 128; k0 += 16) {
        uint32_t aH[4], aL[4], bHa[4], bHb[4], bLa[4], bLb[4];
        ldsm4(aRowQ + k0*2,                   aH[0], aH[1], aH[2], aH[3]);
        ldsm4(aRowQ + (QL_O-QH_O) + k0*2,     aL[0], aL[1], aL[2], aL[3]);
        ldsm4(bRowK + k0*2,                   bHa[0], bHa[1], bHa[2], bHa[3]);
        ldsm4(bRowK + 16*QPB + k0*2,          bHb[0], bHb[1], bHb[2], bHb[3]);
        ldsm4(bRowK + (KL_O-KH_O) + k0*2,         bLa[0], bLa[1], bLa[2], bLa[3]);
        ldsm4(bRowK + (KL_O-KH_O) + 16*QPB + k0*2, bLb[0], bLb[1], bLb[2], bLb[3]);
        mma16816(cA[0], aH, bHa[0], bHa[1]); mma16816(cA[1], aH, bHa[2], bHa[3]);
        mma16816(cA[2], aH, bHb[0], bHb[1]); mma16816(cA[3], aH, bHb[2], bHb[3]);
        mma16816(cA[0], aH, bLa[0], bLa[1]); mma16816(cA[1], aH, bLa[2], bLa[3]);
        mma16816(cA[2], aH, bLb[0], bLb[1]); mma16816(cA[3], aH, bLb[2], bLb[3]);
        mma16816(cA[0], aL, bHa[0], bHa[1]); mma16816(cA[1], aL, bHa[2], bHa[3]);
        mma16816(cA[2], aL, bHb[0], bHb[1]); mma16816(cA[3], aL, bHb[2], bHb[3]);
    }

    {
        int r0g = i0 + (lane >> 2);
        int cb  = n0 + 2 * (lane & 3);
        float rs0 = 0.f, rs1 = 0.f;
        #pragma unroll
        for (int nt = 0; nt < 4; nt++) {
            int j0 = cb + 8 * nt;
            float x0 = (j0     <= r0g    ) ? cA[nt][0] : 0.f;
            float x1 = (j0 + 1 <= r0g    ) ? cA[nt][1] : 0.f;
            float x2 = (j0     <= r0g + 8) ? cA[nt][2] : 0.f;
            float x3 = (j0 + 1 <= r0g + 8) ? cA[nt][3] : 0.f;
            rs0 += x0 + x1; rs1 += x2 + x3;
            uint32_t h0, l0, h1, l1;
            split2(x0, x1, h0, l0); split2(x2, x3, h1, l1);
            uint32_t o0 = r0g * TPB + j0 * 2, o1 = (r0g + 8) * TPB + j0 * 2;
            *(uint32_t*)(smb + AH_O + o0) = h0; *(uint32_t*)(smb + AL_O + o0) = l0;
            *(uint32_t*)(smb + AH_O + o1) = h1; *(uint32_t*)(smb + AL_O + o1) = l1;
        }
        rs0 += __shfl_xor_sync(0xffffffffu, rs0, 1); rs0 += __shfl_xor_sync(0xffffffffu, rs0, 2);
        rs1 += __shfl_xor_sync(0xffffffffu, rs1, 1); rs1 += __shfl_xor_sync(0xffffffffu, rs1, 2);
        if ((lane & 3) == 0) {
            atomicAdd(&den_s[r0g], rs0);
            atomicAdd(&den_s[r0g + 8], rs1);
        }
    }
    __syncthreads();

    float cO[4][4];
    #pragma unroll
    for (int nt = 0; nt < 4; nt++) { cO[nt][0]=0; cO[nt][1]=0; cO[nt][2]=0; cO[nt][3]=0; }
    #pragma unroll
    for (int k0 = 0; k0 < 64; k0 += 16) {
        uint32_t aH[4], aL[4], bHa[4], bHb[4], bLa[4], bLb[4];
        ldsm4(aRowA + k0*2,               aH[0], aH[1], aH[2], aH[3]);
        ldsm4(aRowA + (AL_O-AH_O) + k0*2, aL[0], aL[1], aL[2], aL[3]);
        ldsm4t(bRowV + k0*TPB,                  bHa[0], bHa[1], bHa[2], bHa[3]);
        ldsm4t(bRowV + k0*TPB + 32,             bHb[0], bHb[1], bHb[2], bHb[3]);
        ldsm4t(bRowV + (VL_O-VH_O) + k0*TPB,      bLa[0], bLa[1], bLa[2], bLa[3]);
        ldsm4t(bRowV + (VL_O-VH_O) + k0*TPB + 32, bLb[0], bLb[1], bLb[2], bLb[3]);
        mma16816(cO[0], aH, bHa[0], bHa[1]); mma16816(cO[1], aH, bHa[2], bHa[3]);
        mma16816(cO[2], aH, bHb[0], bHb[1]); mma16816(cO[3], aH, bHb[2], bHb[3]);
        mma16816(cO[0], aL, bHa[0], bHa[1]); mma16816(cO[1], aL, bHa[2], bHa[3]);
        mma16816(cO[2], aL, bHb[0], bHb[1]); mma16816(cO[3], aL, bHb[2], bHb[3]);
        mma16816(cO[0], aH, bLa[0], bLa[1]); mma16816(cO[1], aH, bLa[2], bLa[3]);
        mma16816(cO[2], aH, bLb[0], bLb[1]); mma16816(cO[3], aH, bLb[2], bLb[3]);
    }
    #pragma unroll
    for (int k0 = 0; k0 < 128; k0 += 16) {
        uint32_t aH[4], aL[4], bHa[4], bHb[4], bLa[4], bLb[4];
        ldsm4(aRowQ + k0*2,               aH[0], aH[1], aH[2], aH[3]);
        ldsm4(aRowQ + (QL_O-QH_O) + k0*2, aL[0], aL[1], aL[2], aL[3]);
        ldsm4t(bRowS + k0*TPB,                  bHa[0], bHa[1], bHa[2], bHa[3]);
        ldsm4t(bRowS + k0*TPB + 32,             bHb[0], bHb[1], bHb[2], bHb[3]);
        ldsm4t(bRowS + (SL_O-SH_O) + k0*TPB,      bLa[0], bLa[1], bLa[2], bLa[3]);
        ldsm4t(bRowS + (SL_O-SH_O) + k0*TPB + 32, bLb[0], bLb[1], bLb[2], bLb[3]);
        mma16816(cO[0], aH, bHa[0], bHa[1]); mma16816(cO[1], aH, bHa[2], bHa[3]);
        mma16816(cO[2], aH, bHb[0], bHb[1]); mma16816(cO[3], aH, bHb[2], bHb[3]);
        mma16816(cO[0], aL, bHa[0], bHa[1]); mma16816(cO[1], aL, bHa[2], bHa[3]);
        mma16816(cO[2], aL, bHb[0], bHb[1]); mma16816(cO[3], aL, bHb[2], bHb[3]);
        mma16816(cO[0], aH, bLa[0], bLa[1]); mma16816(cO[1], aH, bLa[2], bLa[3]);
        mma16816(cO[2], aH, bLb[0], bLb[1]); mma16816(cO[3], aH, bLb[2], bLb[3]);
    }

    {
        int r0g = i0 + (lane >> 2);
        int cb  = n0 + 2 * (lane & 3);
        float inv0 = __fdividef(1.f, den_s[r0g]);
        float inv1 = __fdividef(1.f, den_s[r0g + 8]);
        float* orow0 = outg + (((size_t)b * Lc + c*64 + r0g    ) * Hc + h) * Dc;
        float* orow1 = outg + (((size_t)b * Lc + c*64 + r0g + 8) * Hc + h) * Dc;
        #pragma unroll
        for (int nt = 0; nt < 4; nt++) {
            int j0 = cb + 8 * nt;
            *(float2*)(orow0 + j0) = make_float2(cO[nt][0] * inv0, cO[nt][1] * inv0);
            *(float2*)(orow1 + j0) = make_float2(cO[nt][2] * inv1, cO[nt][3] * inv1);
        }
    }
}

// ---------------------------------------------------------------------------
extern "C" void kernel_launch(void* const* d_in, const int* in_sizes, int n_in,
                              void* d_out, int out_size)
{
    const float* q    = (const float*)d_in[0];
    const float* k    = (const float*)d_in[1];
    const float* v    = (const float*)d_in[2];
    const float* proj = (const float*)d_in[3];
    float* out = (float*)d_out;

    cudaFuncSetAttribute(proj_kernel,  cudaFuncAttributeMaxDynamicSharedMemorySize, PJ_SMEM);
    cudaFuncSetAttribute(chunk_kernel, cudaFuncAttributeMaxDynamicSharedMemorySize, CK_SMEM);
    cudaFuncSetAttribute(out_kernel,   cudaFuncAttributeMaxDynamicSharedMemorySize, OUT_SMEM);

    proj_kernel<<<2048, 256, PJ_SMEM>>>(q, k, proj);
    chunk_kernel<<<BH * NCH, 256, CK_SMEM>>>(v);
    prefix_kernel<<<BH * 32, 256>>>();
    out_kernel<<<BH * NCH, 256, OUT_SMEM>>>(v, out);
}

// round 12
// speedup vs baseline: 2.1459x; 1.0045x over previous
#include <cuda_runtime.h>
#include <cuda_bf16.h>
#include <cstdint>

#define Bc 2
#define Lc 4096
#define Hc 8
#define Dc 64
#define Mc 128
#define BH 16
#define NCH 64

// ---- scratch ----
// g_qp/g_kp: packed bf16 h|(l<<16) per element, [bh][chunk][r64][m128]
__device__ uint32_t g_qp[BH * Lc * Mc];
__device__ uint32_t g_kp[BH * Lc * Mc];
// g_state: chunk writes fp32; prefix rewrites packed h|l (in place, read-once)
__device__ float    g_state[BH * NCH * Dc * Mc];
__device__ float    g_ksum[BH * NCH * Mc];
// packed V, [bh*NCH + c][j*64 + d]
__device__ uint32_t g_vsp[BH * Lc * Dc];

// ---- helpers ----
__device__ __forceinline__ uint32_t smem_u32(const void* p) {
    uint32_t a; asm("{ .reg .u64 t; cvta.to.shared.u64 t, %1; cvt.u32.u64 %0, t; }" : "=r"(a) : "l"(p)); return a;
}
__device__ __forceinline__ void ldsm4(uint32_t addr, uint32_t& r0, uint32_t& r1, uint32_t& r2, uint32_t& r3) {
    asm volatile("ldmatrix.sync.aligned.m8n8.x4.shared.b16 {%0,%1,%2,%3}, [%4];"
        : "=r"(r0), "=r"(r1), "=r"(r2), "=r"(r3) : "r"(addr));
}
__device__ __forceinline__ void ldsm4t(uint32_t addr, uint32_t& r0, uint32_t& r1, uint32_t& r2, uint32_t& r3) {
    asm volatile("ldmatrix.sync.aligned.m8n8.x4.trans.shared.b16 {%0,%1,%2,%3}, [%4];"
        : "=r"(r0), "=r"(r1), "=r"(r2), "=r"(r3) : "r"(addr));
}
__device__ __forceinline__ void mma16816(float* c, const uint32_t* a, uint32_t b0, uint32_t b1) {
    asm volatile("mma.sync.aligned.m16n8k16.row.col.f32.bf16.bf16.f32 "
        "{%0,%1,%2,%3}, {%4,%5,%6,%7}, {%8,%9}, {%0,%1,%2,%3};"
        : "+f"(c[0]), "+f"(c[1]), "+f"(c[2]), "+f"(c[3])
        : "r"(a[0]), "r"(a[1]), "r"(a[2]), "r"(a[3]), "r"(b0), "r"(b1));
}
// split a float pair -> bf16x2 hi word + lo word
__device__ __forceinline__ void split2(float a, float b, uint32_t& h, uint32_t& l) {
    __nv_bfloat162 hv = __floats2bfloat162_rn(a, b);
    float ra = a - __bfloat162float(__low2bfloat16(hv));
    float rb = b - __bfloat162float(__high2bfloat16(hv));
    __nv_bfloat162 lv = __floats2bfloat162_rn(ra, rb);
    h = *(uint32_t*)&hv; l = *(uint32_t*)&lv;
}
// pack per-element: from (h0,h1),(l0,l1) -> p0=h0|l0<<16, p1=h1|l1<<16
__device__ __forceinline__ void pack_pair(uint32_t hw, uint32_t lw, uint32_t& p0, uint32_t& p1) {
    p0 = __byte_perm(hw, lw, 0x5410);
    p1 = __byte_perm(hw, lw, 0x7632);
}
// unpack: from p0,p1 -> hw=h0|h1<<16, lw=l0|l1<<16  (same permutation, self-inverse)
__device__ __forceinline__ void unpack_pair(uint32_t p0, uint32_t p1, uint32_t& hw, uint32_t& lw) {
    hw = __byte_perm(p0, p1, 0x5410);
    lw = __byte_perm(p0, p1, 0x7632);
}
__device__ __forceinline__ float rec1(uint32_t p) {   // reconstruct h+l from packed
    return __uint_as_float(p << 16) + __uint_as_float(p & 0xFFFF0000u);
}
__device__ __forceinline__ uint32_t pack1(float a) {
    __nv_bfloat16 hb = __float2bfloat16_rn(a);
    float lf = a - __bfloat162float(hb);
    __nv_bfloat16 lb = __float2bfloat16_rn(lf);
    return (uint32_t)*(uint16_t*)&hb | ((uint32_t)*(uint16_t*)&lb << 16);
}

// ---------------------------------------------------------------------------
// Kernel 0: V pre-split into packed contiguous per-chunk layout.
// ---------------------------------------------------------------------------
__global__ void __launch_bounds__(256)
vsplit_kernel(const float* __restrict__ vg)
{
    int bid = blockIdx.x, bh = bid >> 6, c = bid & 63;
    int b = bh >> 3, h = bh & 7;
    int tid = threadIdx.x;
    uint4* dst = (uint4*)(g_vsp + (size_t)bid * 4096);
    #pragma unroll
    for (int k2 = 0; k2 < 4; k2++) {
        int t = tid + k2 * 256;
        int row = t >> 4, col4 = t & 15;
        float4 v = ((const float4*)(vg + (((size_t)b * Lc + c*64 + row) * Hc + h) * Dc))[col4];
        uint32_t hw01, lw01, hw23, lw23, p0, p1, p2, p3;
        split2(v.x, v.y, hw01, lw01); pack_pair(hw01, lw01, p0, p1);
        split2(v.z, v.w, hw23, lw23); pack_pair(hw23, lw23, p2, p3);
        dst[t] = make_uint4(p0, p1, p2, p3);
    }
}

// ---------------------------------------------------------------------------
// Kernel 1: projection via HMMA bf16-split; output packed h|l uint32 [r][m].
// ---------------------------------------------------------------------------
#define PTB 144
#define PDH_O 0
#define PDL_O 9216
#define PPH_O 18432
#define PPL_O 36864
#define PJ_SMEM 55296

__global__ void __launch_bounds__(256, 2)
proj_kernel(const float* __restrict__ qg, const float* __restrict__ kg, const float* __restrict__ pg)
{
    extern __shared__ __align__(128) char smb[];
    uint32_t sb = smem_u32(smb);
    int tid = threadIdx.x, lane = tid & 31, wid = tid >> 5;
    int bid = blockIdx.x, qk = bid >> 10, bh = (bid >> 6) & 15, ck = bid & 63;
    int b = bh >> 3, h = bh & 7;
    const float* inp = qk ? kg : qg;
    uint32_t* outp = (qk ? g_kp : g_qp) + ((size_t)bh * Lc + ck * 64) * Mc;

    const float4* p4 = (const float4*)pg;
    float4 pbuf[8];
    #pragma unroll
    for (int k2 = 0; k2 < 8; k2++) pbuf[k2] = p4[tid + k2 * 256];
    float4 rbuf[4];
    #pragma unroll
    for (int k2 = 0; k2 < 4; k2++) {
        int t = tid + k2 * 256;
        int r = t >> 4;
        const float4* src = (const float4*)(inp + (((size_t)b * Lc + ck*64 + r) * Hc + h) * Dc);
        rbuf[k2] = src[t & 15];
    }
    #pragma unroll
    for (int k2 = 0; k2 < 8; k2++) {
        int t = tid + k2 * 256;
        int m = t >> 4, d0 = (t & 15) * 4;
        uint32_t h0, l0, h1, l1;
        split2(pbuf[k2].x, pbuf[k2].y, h0, l0);
        split2(pbuf[k2].z, pbuf[k2].w, h1, l1);
        uint32_t off = m * PTB + d0 * 2;
        *(uint2*)(smb + PPH_O + off) = make_uint2(h0, h1);
        *(uint2*)(smb + PPL_O + off) = make_uint2(l0, l1);
    }
    #pragma unroll
    for (int k2 = 0; k2 < 4; k2++) {
        int t = tid + k2 * 256;
        int r = t >> 4, d0 = (t & 15) * 4;
        uint32_t h0, l0, h1, l1;
        split2(rbuf[k2].x, rbuf[k2].y, h0, l0);
        split2(rbuf[k2].z, rbuf[k2].w, h1, l1);
        uint32_t off = r * PTB + d0 * 2;
        *(uint2*)(smb + PDH_O + off) = make_uint2(h0, h1);
        *(uint2*)(smb + PDL_O + off) = make_uint2(l0, l1);
    }
    __syncthreads();

    int rw = wid & 3, cw = wid >> 2;
    int i0 = 16 * rw, n0 = 64 * cw;
    int q4i = lane >> 3, rr = lane & 7;
    uint32_t aRow = sb + PDH_O + (i0 + (lane & 15)) * PTB + (lane >> 4) * 16;
    uint32_t bRow = sb + PPH_O + (n0 + 8 * (q4i >> 1) + rr) * PTB + (q4i & 1) * 16;

    float cO[8][4];
    #pragma unroll
    for (int t8 = 0; t8 < 8; t8++) { cO[t8][0]=0; cO[t8][1]=0; cO[t8][2]=0; cO[t8][3]=0; }

    #pragma unroll
    for (int k0 = 0; k0 < 64; k0 += 16) {
        uint32_t aH[4], aL[4];
        ldsm4(aRow + k0*2,                 aH[0], aH[1], aH[2], aH[3]);
        ldsm4(aRow + (PDL_O-PDH_O) + k0*2, aL[0], aL[1], aL[2], aL[3]);
        uint32_t bH[4][4], bL[4][4];
        #pragma unroll
        for (int nt = 0; nt < 4; nt++) {
            ldsm4(bRow + nt*16*PTB + k0*2,                 bH[nt][0], bH[nt][1], bH[nt][2], bH[nt][3]);
            ldsm4(bRow + (PPL_O-PPH_O) + nt*16*PTB + k0*2, bL[nt][0], bL[nt][1], bL[nt][2], bL[nt][3]);
        }
        #pragma unroll
        for (int nt = 0; nt < 4; nt++) {
            mma16816(cO[2*nt],   aH, bH[nt][0], bH[nt][1]);
            mma16816(cO[2*nt+1], aH, bH[nt][2], bH[nt][3]);
            mma16816(cO[2*nt],   aH, bL[nt][0], bL[nt][1]);
            mma16816(cO[2*nt+1], aH, bL[nt][2], bL[nt][3]);
            mma16816(cO[2*nt],   aL, bH[nt][0], bH[nt][1]);
            mma16816(cO[2*nt+1], aL, bH[nt][2], bH[nt][3]);
        }
    }

    const float ratio = 0.08838834764831845f;
    int r0g = i0 + (lane >> 2);
    int cb  = 2 * (lane & 3);
    #pragma unroll
    for (int t8 = 0; t8 < 8; t8++) {
        int j = n0 + cb + 8 * t8;
        float v0 = cO[t8][0]*ratio, v1 = cO[t8][1]*ratio, v2 = cO[t8][2]*ratio, v3 = cO[t8][3]*ratio;
        v0 = (v0 > 0.f ? v0 : 0.f) + 1e-3f; v1 = (v1 > 0.f ? v1 : 0.f) + 1e-3f;
        v2 = (v2 > 0.f ? v2 : 0.f) + 1e-3f; v3 = (v3 > 0.f ? v3 : 0.f) + 1e-3f;
        uint32_t hw, lw, p0, p1;
        split2(v0, v1, hw, lw); pack_pair(hw, lw, p0, p1);
        *(uint2*)&outp[r0g * Mc + j] = make_uint2(p0, p1);
        split2(v2, v3, hw, lw); pack_pair(hw, lw, p0, p1);
        *(uint2*)&outp[(r0g + 8) * Mc + j] = make_uint2(p0, p1);
    }
}

// ---------------------------------------------------------------------------
// Kernel 2: S[m][d] = K^T V via HMMA bf16-split (packed inputs).
// ---------------------------------------------------------------------------
#define KPB 272
#define VPB 144
#define CKH_O 0
#define CKL_O 17408
#define CVH_O 34816
#define CVL_O 44032
#define CK_SMEM 53248

__global__ void __launch_bounds__(256, 2)
chunk_kernel()
{
    extern __shared__ __align__(128) char smb[];
    uint32_t sb = smem_u32(smb);
    int tid = threadIdx.x, lane = tid & 31, wid = tid >> 5;
    int bh = blockIdx.x >> 6;

    const uint32_t* kq = &g_kp[((size_t)bh * Lc + (blockIdx.x & 63) * 64) * Mc];  // [c][m] packed
    const uint4* k4 = (const uint4*)kq;
    const uint4* v4 = (const uint4*)(g_vsp + (size_t)blockIdx.x * 4096);

    uint4 kbuf[8];
    #pragma unroll
    for (int k2 = 0; k2 < 8; k2++) kbuf[k2] = k4[tid + k2 * 256];
    uint4 vbuf[4];
    #pragma unroll
    for (int k2 = 0; k2 < 4; k2++) vbuf[k2] = v4[tid + k2 * 256];

    #pragma unroll
    for (int k2 = 0; k2 < 8; k2++) {
        int t = tid + k2 * 256;
        int cc = t >> 5, m4 = (t & 31) * 4;
        uint32_t hw01, lw01, hw23, lw23;
        unpack_pair(kbuf[k2].x, kbuf[k2].y, hw01, lw01);
        unpack_pair(kbuf[k2].z, kbuf[k2].w, hw23, lw23);
        uint32_t off = cc * KPB + m4 * 2;
        *(uint2*)(smb + CKH_O + off) = make_uint2(hw01, hw23);
        *(uint2*)(smb + CKL_O + off) = make_uint2(lw01, lw23);
    }
    #pragma unroll
    for (int k2 = 0; k2 < 4; k2++) {
        int t = tid + k2 * 256;
        int row = t >> 4, d4 = (t & 15) * 4;
        uint32_t hw01, lw01, hw23, lw23;
        unpack_pair(vbuf[k2].x, vbuf[k2].y, hw01, lw01);
        unpack_pair(vbuf[k2].z, vbuf[k2].w, hw23, lw23);
        uint32_t off = row * VPB + d4 * 2;
        *(uint2*)(smb + CVH_O + off) = make_uint2(hw01, hw23);
        *(uint2*)(smb + CVL_O + off) = make_uint2(lw01, lw23);
    }
    __syncthreads();

    int i0 = wid * 16;
    int q4i = lane >> 3, rr = lane & 7;
    uint32_t aRow = sb + CKH_O + (8 * (lane >> 4) + rr) * KPB + (i0 + 8 * (q4i & 1)) * 2;
    uint32_t bRow = sb + CVH_O + (8 * (q4i & 1) + rr) * VPB + (8 * (q4i >> 1)) * 2;

    float cS[8][4];
    #pragma unroll
    for (int t8 = 0; t8 < 8; t8++) { cS[t8][0]=0; cS[t8][1]=0; cS[t8][2]=0; cS[t8][3]=0; }

    #pragma unroll
    for (int c0 = 0; c0 < 64; c0 += 16) {
        uint32_t aH[4], aL[4];
        ldsm4t(aRow + c0*KPB,                 aH[0], aH[1], aH[2], aH[3]);
        ldsm4t(aRow + (CKL_O-CKH_O) + c0*KPB, aL[0], aL[1], aL[2], aL[3]);
        uint32_t bH[4][4], bL[4][4];
        #pragma unroll
        for (int nt = 0; nt < 4; nt++) {
            ldsm4t(bRow + c0*VPB + nt*32,                 bH[nt][0], bH[nt][1], bH[nt][2], bH[nt][3]);
            ldsm4t(bRow + (CVL_O-CVH_O) + c0*VPB + nt*32, bL[nt][0], bL[nt][1], bL[nt][2], bL[nt][3]);
        }
        #pragma unroll
        for (int nt = 0; nt < 4; nt++) {
            mma16816(cS[2*nt],   aH, bH[nt][0], bH[nt][1]);
            mma16816(cS[2*nt+1], aH, bH[nt][2], bH[nt][3]);
            mma16816(cS[2*nt],   aH, bL[nt][0], bL[nt][1]);
            mma16816(cS[2*nt+1], aH, bL[nt][2], bL[nt][3]);
            mma16816(cS[2*nt],   aL, bH[nt][0], bH[nt][1]);
            mma16816(cS[2*nt+1], aL, bH[nt][2], bH[nt][3]);
        }
    }

    float* Sp = &g_state[(size_t)blockIdx.x * (Dc * Mc)];
    int m0g = i0 + (lane >> 2);
    int cb  = 2 * (lane & 3);
    #pragma unroll
    for (int t8 = 0; t8 < 8; t8++) {
        int d = cb + 8 * t8;
        *(float2*)&Sp[m0g * 64 + d]       = make_float2(cS[t8][0], cS[t8][1]);
        *(float2*)&Sp[(m0g + 8) * 64 + d] = make_float2(cS[t8][2], cS[t8][3]);
    }

    // z[m] exact fp32 from packed K (hot in L2)
    if (tid < 128) {
        float z = 0.f;
        #pragma unroll
        for (int cc = 0; cc < 64; cc++) z += rec1(kq[cc * Mc + tid]);
        g_ksum[(size_t)blockIdx.x * Mc + tid] = z;
    }
}

// ---------------------------------------------------------------------------
// Kernel 3: exclusive prefix over chunks; writes PACKED h|l state in place.
// ---------------------------------------------------------------------------
__global__ void prefix_kernel()
{
    int bh = blockIdx.x >> 5, slice = blockIdx.x & 31;
    int e = slice * 256 + threadIdx.x;
    size_t base = (size_t)bh * NCH * (Dc * Mc) + e;
    float acc = 0.f;
    #pragma unroll 1
    for (int c0 = 0; c0 < 64; c0 += 8) {
        float v[8];
        #pragma unroll
        for (int u = 0; u < 8; u++) v[u] = g_state[base + (size_t)(c0 + u) * (Dc * Mc)];
        #pragma unroll
        for (int u = 0; u < 8; u++) {
            ((uint32_t*)g_state)[base + (size_t)(c0 + u) * (Dc * Mc)] = pack1(acc);
            acc += v[u];
        }
    }
    if (slice == 0 && threadIdx.x < 128) {
        size_t kb = (size_t)bh * NCH * Mc + threadIdx.x;
        float a2 = 0.f;
        #pragma unroll 1
        for (int c = 0; c < 64; c++) { float t = g_ksum[kb + (size_t)c * Mc]; g_ksum[kb + (size_t)c * Mc] = a2; a2 += t; }
    }
}

// ---------------------------------------------------------------------------
// Kernel 4: out_kernel, 2 CTAs/SM.  K-region unioned with S-region.
// ---------------------------------------------------------------------------
#define QPB 272
#define TPB 144
#define QH_O 0
#define QL_O 17408
#define U_O  34816         // KH=U_O, KL=U_O+17408 | SH=U_O, SL=U_O+18432
#define VH_O 71680
#define VL_O 80896
#define AH_O 90112
#define AL_O 99328
#define KS_O 108544
#define DEN_O 109056
#define OUT_SMEM 109312

__global__ void __launch_bounds__(256, 2)
out_kernel(float* __restrict__ outg)
{
    extern __shared__ __align__(128) char smb[];
    uint32_t sb = smem_u32(smb);
    float* ks_s  = (float*)(smb + KS_O);
    float* den_s = (float*)(smb + DEN_O);

    int tid = threadIdx.x, lane = tid & 31, wid = tid >> 5;
    int bh = blockIdx.x >> 6, c = blockIdx.x & 63;
    int b = bh >> 3, h = bh & 7;

    const uint32_t* qt = g_qp + (size_t)blockIdx.x * (64 * Mc);
    const uint32_t* kt = g_kp + (size_t)blockIdx.x * (64 * Mc);
    const uint4* q4 = (const uint4*)qt;
    const uint4* k4 = (const uint4*)kt;
    const uint4* s4 = (const uint4*)((const uint32_t*)g_state + (size_t)blockIdx.x * (Mc * Dc));
    const uint4* v4 = (const uint4*)(g_vsp + (size_t)blockIdx.x * 4096);

    if (tid < 128) ks_s[tid] = g_ksum[(size_t)blockIdx.x * Mc + tid];

    // S prefetched into registers; scattered into the K region after GEMM1
    uint4 sbuf[8];
    #pragma unroll
    for (int k2 = 0; k2 < 8; k2++) sbuf[k2] = s4[tid + k2 * 256];

    // Q tile
    {
        uint4 buf[8];
        #pragma unroll
        for (int k2 = 0; k2 < 8; k2++) buf[k2] = q4[tid + k2 * 256];
        #pragma unroll
        for (int k2 = 0; k2 < 8; k2++) {
            int t = tid + k2 * 256;
            int r = t >> 5, m4 = (t & 31) * 4;
            uint32_t hw01, lw01, hw23, lw23;
            unpack_pair(buf[k2].x, buf[k2].y, hw01, lw01);
            unpack_pair(buf[k2].z, buf[k2].w, hw23, lw23);
            uint32_t off = r * QPB + m4 * 2;
            *(uint2*)(smb + QH_O + off) = make_uint2(hw01, hw23);
            *(uint2*)(smb + QL_O + off) = make_uint2(lw01, lw23);
        }
    }
    // K tile -> union region
    {
        uint4 buf[8];
        #pragma unroll
        for (int k2 = 0; k2 < 8; k2++) buf[k2] = k4[tid + k2 * 256];
        #pragma unroll
        for (int k2 = 0; k2 < 8; k2++) {
            int t = tid + k2 * 256;
            int r = t >> 5, m4 = (t & 31) * 4;
            uint32_t hw01, lw01, hw23, lw23;
            unpack_pair(buf[k2].x, buf[k2].y, hw01, lw01);
            unpack_pair(buf[k2].z, buf[k2].w, hw23, lw23);
            uint32_t off = r * QPB + m4 * 2;
            *(uint2*)(smb + U_O + off)         = make_uint2(hw01, hw23);
            *(uint2*)(smb + U_O + 17408 + off) = make_uint2(lw01, lw23);
        }
    }
    // V tile
    {
        uint4 buf[4];
        #pragma unroll
        for (int k2 = 0; k2 < 4; k2++) buf[k2] = v4[tid + k2 * 256];
        #pragma unroll
        for (int k2 = 0; k2 < 4; k2++) {
            int t = tid + k2 * 256;
            int row = t >> 4, d4 = (t & 15) * 4;
            uint32_t hw01, lw01, hw23, lw23;
            unpack_pair(buf[k2].x, buf[k2].y, hw01, lw01);
            unpack_pair(buf[k2].z, buf[k2].w, hw23, lw23);
            uint32_t off = row * TPB + d4 * 2;
            *(uint2*)(smb + VH_O + off) = make_uint2(hw01, hw23);
            *(uint2*)(smb + VL_O + off) = make_uint2(lw01, lw23);
        }
    }
    __syncthreads();

    // den init: Q . ksum from packed global (h+l reconstruction)
    if (tid < 64) {
        const uint4* qr = (const uint4*)(qt + tid * Mc);
        float qd = 0.f;
        #pragma unroll
        for (int m4 = 0; m4 < 32; m4++) {
            uint4 p = qr[m4];
            qd += rec1(p.x) * ks_s[4*m4]   + rec1(p.y) * ks_s[4*m4+1]
                + rec1(p.z) * ks_s[4*m4+2] + rec1(p.w) * ks_s[4*m4+3];
        }
        den_s[tid] = qd;
    }
    // den init must happen-before the atomicAdd rowsum accumulation below.
    __syncthreads();

    int rw = wid & 3, cw = wid >> 2;
    int i0 = 16 * rw, n0 = 32 * cw;
    int q4i = lane >> 3, rr = lane & 7;

    uint32_t aRowQ = sb + QH_O + (i0 + (lane & 15)) * QPB + (lane >> 4) * 16;
    uint32_t bRowK = sb + U_O  + (n0 + 8 * (q4i >> 1) + rr) * QPB + (q4i & 1) * 16;
    uint32_t aRowA = sb + AH_O + (i0 + (lane & 15)) * TPB + (lane >> 4) * 16;
    uint32_t bRowV = sb + VH_O + (8 * (q4i & 1) + rr) * TPB + (n0 + 8 * (q4i >> 1)) * 2;
    uint32_t bRowS = sb + U_O  + (8 * (q4i & 1) + rr) * TPB + (n0 + 8 * (q4i >> 1)) * 2;

    // ---- GEMM1: A = Q K^T ----
    float cA[4][4];
    #pragma unroll
    for (int nt = 0; nt < 4; nt++) { cA[nt][0]=0; cA[nt][1]=0; cA[nt][2]=0; cA[nt][3]=0; }
    #pragma unroll
    for (int k0 = 0; k0 < 128; k0 += 16) {
        uint32_t aH[4], aL[4], bHa[4], bHb[4], bLa[4], bLb[4];
        ldsm4(aRowQ + k0*2,               aH[0], aH[1], aH[2], aH[3]);
        ldsm4(aRowQ + (QL_O-QH_O) + k0*2, aL[0], aL[1], aL[2], aL[3]);
        ldsm4(bRowK + k0*2,               bHa[0], bHa[1], bHa[2], bHa[3]);
        ldsm4(bRowK + 16*QPB + k0*2,      bHb[0], bHb[1], bHb[2], bHb[3]);
        ldsm4(bRowK + 17408 + k0*2,           bLa[0], bLa[1], bLa[2], bLa[3]);
        ldsm4(bRowK + 17408 + 16*QPB + k0*2,  bLb[0], bLb[1], bLb[2], bLb[3]);
        mma16816(cA[0], aH, bHa[0], bHa[1]); mma16816(cA[1], aH, bHa[2], bHa[3]);
        mma16816(cA[2], aH, bHb[0], bHb[1]); mma16816(cA[3], aH, bHb[2], bHb[3]);
        mma16816(cA[0], aH, bLa[0], bLa[1]); mma16816(cA[1], aH, bLa[2], bLa[3]);
        mma16816(cA[2], aH, bLb[0], bLb[1]); mma16816(cA[3], aH, bLb[2], bLb[3]);
        mma16816(cA[0], aL, bHa[0], bHa[1]); mma16816(cA[1], aL, bHa[2], bHa[3]);
        mma16816(cA[2], aL, bHb[0], bHb[1]); mma16816(cA[3], aL, bHb[2], bHb[3]);
    }

    // ---- mask, rowsum, split-store A ----
    {
        int r0g = i0 + (lane >> 2);
        int cb  = n0 + 2 * (lane & 3);
        float rs0 = 0.f, rs1 = 0.f;
        #pragma unroll
        for (int nt = 0; nt < 4; nt++) {
            int j0 = cb + 8 * nt;
            float x0 = (j0     <= r0g    ) ? cA[nt][0] : 0.f;
            float x1 = (j0 + 1 <= r0g    ) ? cA[nt][1] : 0.f;
            float x2 = (j0     <= r0g + 8) ? cA[nt][2] : 0.f;
            float x3 = (j0 + 1 <= r0g + 8) ? cA[nt][3] : 0.f;
            rs0 += x0 + x1; rs1 += x2 + x3;
            uint32_t h0, l0, h1, l1;
            split2(x0, x1, h0, l0); split2(x2, x3, h1, l1);
            uint32_t o0 = r0g * TPB + j0 * 2, o1 = (r0g + 8) * TPB + j0 * 2;
            *(uint32_t*)(smb + AH_O + o0) = h0; *(uint32_t*)(smb + AL_O + o0) = l0;
            *(uint32_t*)(smb + AH_O + o1) = h1; *(uint32_t*)(smb + AL_O + o1) = l1;
        }
        rs0 += __shfl_xor_sync(0xffffffffu, rs0, 1); rs0 += __shfl_xor_sync(0xffffffffu, rs0, 2);
        rs1 += __shfl_xor_sync(0xffffffffu, rs1, 1); rs1 += __shfl_xor_sync(0xffffffffu, rs1, 2);
        if ((lane & 3) == 0) {
            atomicAdd(&den_s[r0g], rs0);
            atomicAdd(&den_s[r0g + 8], rs1);
        }
    }
    __syncthreads();   // K reads done; A complete

    // scatter S (from registers) into union region
    #pragma unroll
    for (int k2 = 0; k2 < 8; k2++) {
        int t = tid + k2 * 256;
        int m = t >> 4, d4 = (t & 15) * 4;
        uint32_t hw01, lw01, hw23, lw23;
        unpack_pair(sbuf[k2].x, sbuf[k2].y, hw01, lw01);
        unpack_pair(sbuf[k2].z, sbuf[k2].w, hw23, lw23);
        uint32_t off = m * TPB + d4 * 2;
        *(uint2*)(smb + U_O + off)         = make_uint2(hw01, hw23);
        *(uint2*)(smb + U_O + 18432 + off) = make_uint2(lw01, lw23);
    }
    __syncthreads();

    // ---- GEMM2: num = A V + Q S ----
    float cO[4][4];
    #pragma unroll
    for (int nt = 0; nt < 4; nt++) { cO[nt][0]=0; cO[nt][1]=0; cO[nt][2]=0; cO[nt][3]=0; }
    #pragma unroll
    for (int k0 = 0; k0 < 64; k0 += 16) {
        uint32_t aH[4], aL[4], bHa[4], bHb[4], bLa[4], bLb[4];
        ldsm4(aRowA + k0*2,               aH[0], aH[1], aH[2], aH[3]);
        ldsm4(aRowA + (AL_O-AH_O) + k0*2, aL[0], aL[1], aL[2], aL[3]);
        ldsm4t(bRowV + k0*TPB,                  bHa[0], bHa[1], bHa[2], bHa[3]);
        ldsm4t(bRowV + k0*TPB + 32,             bHb[0], bHb[1], bHb[2], bHb[3]);
        ldsm4t(bRowV + (VL_O-VH_O) + k0*TPB,      bLa[0], bLa[1], bLa[2], bLa[3]);
        ldsm4t(bRowV + (VL_O-VH_O) + k0*TPB + 32, bLb[0], bLb[1], bLb[2], bLb[3]);
        mma16816(cO[0], aH, bHa[0], bHa[1]); mma16816(cO[1], aH, bHa[2], bHa[3]);
        mma16816(cO[2], aH, bHb[0], bHb[1]); mma16816(cO[3], aH, bHb[2], bHb[3]);
        mma16816(cO[0], aL, bHa[0], bHa[1]); mma16816(cO[1], aL, bHa[2], bHa[3]);
        mma16816(cO[2], aL, bHb[0], bHb[1]); mma16816(cO[3], aL, bHb[2], bHb[3]);
        mma16816(cO[0], aH, bLa[0], bLa[1]); mma16816(cO[1], aH, bLa[2], bLa[3]);
        mma16816(cO[2], aH, bLb[0], bLb[1]); mma16816(cO[3], aH, bLb[2], bLb[3]);
    }
    #pragma unroll
    for (int k0 = 0; k0 < 128; k0 += 16) {
        uint32_t aH[4], aL[4], bHa[4], bHb[4], bLa[4], bLb[4];
        ldsm4(aRowQ + k0*2,               aH[0], aH[1], aH[2], aH[3]);
        ldsm4(aRowQ + (QL_O-QH_O) + k0*2, aL[0], aL[1], aL[2], aL[3]);
        ldsm4t(bRowS + k0*TPB,            bHa[0], bHa[1], bHa[2], bHa[3]);
        ldsm4t(bRowS + k0*TPB + 32,       bHb[0], bHb[1], bHb[2], bHb[3]);
        ldsm4t(bRowS + 18432 + k0*TPB,      bLa[0], bLa[1], bLa[2], bLa[3]);
        ldsm4t(bRowS + 18432 + k0*TPB + 32, bLb[0], bLb[1], bLb[2], bLb[3]);
        mma16816(cO[0], aH, bHa[0], bHa[1]); mma16816(cO[1], aH, bHa[2], bHa[3]);
        mma16816(cO[2], aH, bHb[0], bHb[1]); mma16816(cO[3], aH, bHb[2], bHb[3]);
        mma16816(cO[0], aL, bHa[0], bHa[1]); mma16816(cO[1], aL, bHa[2], bHa[3]);
        mma16816(cO[2], aL, bHb[0], bHb[1]); mma16816(cO[3], aL, bHb[2], bHb[3]);
        mma16816(cO[0], aH, bLa[0], bLa[1]); mma16816(cO[1], aH, bLa[2], bLa[3]);
        mma16816(cO[2], aH, bLb[0], bLb[1]); mma16816(cO[3], aH, bLb[2], bLb[3]);
    }

    // ---- normalize + store ----
    {
        int r0g = i0 + (lane >> 2);
        int cb  = n0 + 2 * (lane & 3);
        float inv0 = __fdividef(1.f, den_s[r0g]);
        float inv1 = __fdividef(1.f, den_s[r0g + 8]);
        float* orow0 = outg + (((size_t)b * Lc + c*64 + r0g    ) * Hc + h) * Dc;
        float* orow1 = outg + (((size_t)b * Lc + c*64 + r0g + 8) * Hc + h) * Dc;
        #pragma unroll
        for (int nt = 0; nt < 4; nt++) {
            int j0 = cb + 8 * nt;
            *(float2*)(orow0 + j0) = make_float2(cO[nt][0] * inv0, cO[nt][1] * inv0);
            *(float2*)(orow1 + j0) = make_float2(cO[nt][2] * inv1, cO[nt][3] * inv1);
        }
    }
}

// ---------------------------------------------------------------------------
extern "C" void kernel_launch(void* const* d_in, const int* in_sizes, int n_in,
                              void* d_out, int out_size)
{
    const float* q    = (const float*)d_in[0];
    const float* k    = (const float*)d_in[1];
    const float* v    = (const float*)d_in[2];
    const float* proj = (const float*)d_in[3];
    float* out = (float*)d_out;

    cudaFuncSetAttribute(proj_kernel,  cudaFuncAttributeMaxDynamicSharedMemorySize, PJ_SMEM);
    cudaFuncSetAttribute(chunk_kernel, cudaFuncAttributeMaxDynamicSharedMemorySize, CK_SMEM);
    cudaFuncSetAttribute(out_kernel,   cudaFuncAttributeMaxDynamicSharedMemorySize, OUT_SMEM);

    vsplit_kernel<<<BH * NCH, 256>>>(v);
    proj_kernel<<<2048, 256, PJ_SMEM>>>(q, k, proj);
    chunk_kernel<<<BH * NCH, 256, CK_SMEM>>>();
    prefix_kernel<<<BH * 32, 256>>>();
    out_kernel<<<BH * NCH, 256, OUT_SMEM>>>(out);
}

// round 17
// speedup vs baseline: 2.3973x; 1.1171x over previous
#include <cuda_runtime.h>
#include <cuda_bf16.h>
#include <cstdint>

#define Bc 2
#define Lc 4096
#define Hc 8
#define Dc 64
#define Mc 128
#define BH 16
#define NCH 64

// ---- scratch ----
__device__ uint32_t g_qp[BH * Lc * Mc];
__device__ uint32_t g_kp[BH * Lc * Mc];
__device__ float    g_state[BH * NCH * Dc * Mc];
__device__ float    g_ksum[BH * NCH * Mc];
__device__ uint32_t g_vsp[BH * Lc * Dc];

// ---- helpers ----
__device__ __forceinline__ uint32_t smem_u32(const void* p) {
    uint32_t a; asm("{ .reg .u64 t; cvta.to.shared.u64 t, %1; cvt.u32.u64 %0, t; }" : "=r"(a) : "l"(p)); return a;
}
__device__ __forceinline__ void ldsm4(uint32_t addr, uint32_t& r0, uint32_t& r1, uint32_t& r2, uint32_t& r3) {
    asm volatile("ldmatrix.sync.aligned.m8n8.x4.shared.b16 {%0,%1,%2,%3}, [%4];"
        : "=r"(r0), "=r"(r1), "=r"(r2), "=r"(r3) : "r"(addr));
}
__device__ __forceinline__ void ldsm4t(uint32_t addr, uint32_t& r0, uint32_t& r1, uint32_t& r2, uint32_t& r3) {
    asm volatile("ldmatrix.sync.aligned.m8n8.x4.trans.shared.b16 {%0,%1,%2,%3}, [%4];"
        : "=r"(r0), "=r"(r1), "=r"(r2), "=r"(r3) : "r"(addr));
}
__device__ __forceinline__ void mma16816(float* c, const uint32_t* a, uint32_t b0, uint32_t b1) {
    asm volatile("mma.sync.aligned.m16n8k16.row.col.f32.bf16.bf16.f32 "
        "{%0,%1,%2,%3}, {%4,%5,%6,%7}, {%8,%9}, {%0,%1,%2,%3};"
        : "+f"(c[0]), "+f"(c[1]), "+f"(c[2]), "+f"(c[3])
        : "r"(a[0]), "r"(a[1]), "r"(a[2]), "r"(a[3]), "r"(b0), "r"(b1));
}
__device__ __forceinline__ void split2(float a, float b, uint32_t& h, uint32_t& l) {
    __nv_bfloat162 hv = __floats2bfloat162_rn(a, b);
    float ra = a - __bfloat162float(__low2bfloat16(hv));
    float rb = b - __bfloat162float(__high2bfloat16(hv));
    __nv_bfloat162 lv = __floats2bfloat162_rn(ra, rb);
    h = *(uint32_t*)&hv; l = *(uint32_t*)&lv;
}
__device__ __forceinline__ void pack_pair(uint32_t hw, uint32_t lw, uint32_t& p0, uint32_t& p1) {
    p0 = __byte_perm(hw, lw, 0x5410);
    p1 = __byte_perm(hw, lw, 0x7632);
}
__device__ __forceinline__ void unpack_pair(uint32_t p0, uint32_t p1, uint32_t& hw, uint32_t& lw) {
    hw = __byte_perm(p0, p1, 0x5410);
    lw = __byte_perm(p0, p1, 0x7632);
}
__device__ __forceinline__ float rec1(uint32_t p) {
    return __uint_as_float(p << 16) + __uint_as_float(p & 0xFFFF0000u);
}
__device__ __forceinline__ uint32_t pack1(float a) {
    __nv_bfloat16 hb = __float2bfloat16_rn(a);
    float lf = a - __bfloat162float(hb);
    __nv_bfloat16 lb = __float2bfloat16_rn(lf);
    return (uint32_t)*(uint16_t*)&hb | ((uint32_t)*(uint16_t*)&lb << 16);
}

// ---------------------------------------------------------------------------
// Kernel 0: V pre-split into packed contiguous per-chunk layout.
// ---------------------------------------------------------------------------
__global__ void __launch_bounds__(256)
vsplit_kernel(const float* __restrict__ vg)
{
    int bid = blockIdx.x, bh = bid >> 6, c = bid & 63;
    int b = bh >> 3, h = bh & 7;
    int tid = threadIdx.x;
    uint4* dst = (uint4*)(g_vsp + (size_t)bid * 4096);
    #pragma unroll
    for (int k2 = 0; k2 < 4; k2++) {
        int t = tid + k2 * 256;
        int row = t >> 4, col4 = t & 15;
        float4 v = ((const float4*)(vg + (((size_t)b * Lc + c*64 + row) * Hc + h) * Dc))[col4];
        uint32_t hw01, lw01, hw23, lw23, p0, p1, p2, p3;
        split2(v.x, v.y, hw01, lw01); pack_pair(hw01, lw01, p0, p1);
        split2(v.z, v.w, hw23, lw23); pack_pair(hw23, lw23, p2, p3);
        dst[t] = make_uint4(p0, p1, p2, p3);
    }
}

// ---------------------------------------------------------------------------
// Kernel 1: projection via HMMA bf16-split; output packed h|l uint32 [r][m].
// ---------------------------------------------------------------------------
#define PTB 144
#define PDH_O 0
#define PDL_O 9216
#define PPH_O 18432
#define PPL_O 36864
#define PJ_SMEM 55296

__global__ void __launch_bounds__(256, 2)
proj_kernel(const float* __restrict__ qg, const float* __restrict__ kg, const float* __restrict__ pg)
{
    extern __shared__ __align__(128) char smb[];
    uint32_t sb = smem_u32(smb);
    int tid = threadIdx.x, lane = tid & 31, wid = tid >> 5;
    int bid = blockIdx.x, qk = bid >> 10, bh = (bid >> 6) & 15, ck = bid & 63;
    int b = bh >> 3, h = bh & 7;
    const float* inp = qk ? kg : qg;
    uint32_t* outp = (qk ? g_kp : g_qp) + ((size_t)bh * Lc + ck * 64) * Mc;

    const float4* p4 = (const float4*)pg;
    float4 pbuf[8];
    #pragma unroll
    for (int k2 = 0; k2 < 8; k2++) pbuf[k2] = p4[tid + k2 * 256];
    float4 rbuf[4];
    #pragma unroll
    for (int k2 = 0; k2 < 4; k2++) {
        int t = tid + k2 * 256;
        int r = t >> 4;
        const float4* src = (const float4*)(inp + (((size_t)b * Lc + ck*64 + r) * Hc + h) * Dc);
        rbuf[k2] = src[t & 15];
    }
    #pragma unroll
    for (int k2 = 0; k2 < 8; k2++) {
        int t = tid + k2 * 256;
        int m = t >> 4, d0 = (t & 15) * 4;
        uint32_t h0, l0, h1, l1;
        split2(pbuf[k2].x, pbuf[k2].y, h0, l0);
        split2(pbuf[k2].z, pbuf[k2].w, h1, l1);
        uint32_t off = m * PTB + d0 * 2;
        *(uint2*)(smb + PPH_O + off) = make_uint2(h0, h1);
        *(uint2*)(smb + PPL_O + off) = make_uint2(l0, l1);
    }
    #pragma unroll
    for (int k2 = 0; k2 < 4; k2++) {
        int t = tid + k2 * 256;
        int r = t >> 4, d0 = (t & 15) * 4;
        uint32_t h0, l0, h1, l1;
        split2(rbuf[k2].x, rbuf[k2].y, h0, l0);
        split2(rbuf[k2].z, rbuf[k2].w, h1, l1);
        uint32_t off = r * PTB + d0 * 2;
        *(uint2*)(smb + PDH_O + off) = make_uint2(h0, h1);
        *(uint2*)(smb + PDL_O + off) = make_uint2(l0, l1);
    }
    __syncthreads();

    int rw = wid & 3, cw = wid >> 2;
    int i0 = 16 * rw, n0 = 64 * cw;
    int q4i = lane >> 3, rr = lane & 7;
    uint32_t aRow = sb + PDH_O + (i0 + (lane & 15)) * PTB + (lane >> 4) * 16;
    uint32_t bRow = sb + PPH_O + (n0 + 8 * (q4i >> 1) + rr) * PTB + (q4i & 1) * 16;

    float cO[8][4];
    #pragma unroll
    for (int t8 = 0; t8 < 8; t8++) { cO[t8][0]=0; cO[t8][1]=0; cO[t8][2]=0; cO[t8][3]=0; }

    #pragma unroll
    for (int k0 = 0; k0 < 64; k0 += 16) {
        uint32_t aH[4], aL[4];
        ldsm4(aRow + k0*2,                 aH[0], aH[1], aH[2], aH[3]);
        ldsm4(aRow + (PDL_O-PDH_O) + k0*2, aL[0], aL[1], aL[2], aL[3]);
        uint32_t bH[4][4], bL[4][4];
        #pragma unroll
        for (int nt = 0; nt < 4; nt++) {
            ldsm4(bRow + nt*16*PTB + k0*2,                 bH[nt][0], bH[nt][1], bH[nt][2], bH[nt][3]);
            ldsm4(bRow + (PPL_O-PPH_O) + nt*16*PTB + k0*2, bL[nt][0], bL[nt][1], bL[nt][2], bL[nt][3]);
        }
        #pragma unroll
        for (int nt = 0; nt < 4; nt++) {
            mma16816(cO[2*nt],   aH, bH[nt][0], bH[nt][1]);
            mma16816(cO[2*nt+1], aH, bH[nt][2], bH[nt][3]);
            mma16816(cO[2*nt],   aH, bL[nt][0], bL[nt][1]);
            mma16816(cO[2*nt+1], aH, bL[nt][2], bL[nt][3]);
            mma16816(cO[2*nt],   aL, bH[nt][0], bH[nt][1]);
            mma16816(cO[2*nt+1], aL, bH[nt][2], bH[nt][3]);
        }
    }

    const float ratio = 0.08838834764831845f;
    int r0g = i0 + (lane >> 2);
    int cb  = 2 * (lane & 3);
    #pragma unroll
    for (int t8 = 0; t8 < 8; t8++) {
        int j = n0 + cb + 8 * t8;
        float v0 = cO[t8][0]*ratio, v1 = cO[t8][1]*ratio, v2 = cO[t8][2]*ratio, v3 = cO[t8][3]*ratio;
        v0 = (v0 > 0.f ? v0 : 0.f) + 1e-3f; v1 = (v1 > 0.f ? v1 : 0.f) + 1e-3f;
        v2 = (v2 > 0.f ? v2 : 0.f) + 1e-3f; v3 = (v3 > 0.f ? v3 : 0.f) + 1e-3f;
        uint32_t hw, lw, p0, p1;
        split2(v0, v1, hw, lw); pack_pair(hw, lw, p0, p1);
        *(uint2*)&outp[r0g * Mc + j] = make_uint2(p0, p1);
        split2(v2, v3, hw, lw); pack_pair(hw, lw, p0, p1);
        *(uint2*)&outp[(r0g + 8) * Mc + j] = make_uint2(p0, p1);
    }
}

// ---------------------------------------------------------------------------
// Kernel 2: S[m][d] = K^T V via HMMA bf16-split (packed inputs).
// ---------------------------------------------------------------------------
#define KPB 272
#define VPB 144
#define CKH_O 0
#define CKL_O 17408
#define CVH_O 34816
#define CVL_O 44032
#define CK_SMEM 53248

__global__ void __launch_bounds__(256, 2)
chunk_kernel()
{
    extern __shared__ __align__(128) char smb[];
    uint32_t sb = smem_u32(smb);
    int tid = threadIdx.x, lane = tid & 31, wid = tid >> 5;
    int bh = blockIdx.x >> 6;

    const uint32_t* kq = &g_kp[((size_t)bh * Lc + (blockIdx.x & 63) * 64) * Mc];
    const uint4* k4 = (const uint4*)kq;
    const uint4* v4 = (const uint4*)(g_vsp + (size_t)blockIdx.x * 4096);

    uint4 kbuf[8];
    #pragma unroll
    for (int k2 = 0; k2 < 8; k2++) kbuf[k2] = k4[tid + k2 * 256];
    uint4 vbuf[4];
    #pragma unroll
    for (int k2 = 0; k2 < 4; k2++) vbuf[k2] = v4[tid + k2 * 256];

    #pragma unroll
    for (int k2 = 0; k2 < 8; k2++) {
        int t = tid + k2 * 256;
        int cc = t >> 5, m4 = (t & 31) * 4;
        uint32_t hw01, lw01, hw23, lw23;
        unpack_pair(kbuf[k2].x, kbuf[k2].y, hw01, lw01);
        unpack_pair(kbuf[k2].z, kbuf[k2].w, hw23, lw23);
        uint32_t off = cc * KPB + m4 * 2;
        *(uint2*)(smb + CKH_O + off) = make_uint2(hw01, hw23);
        *(uint2*)(smb + CKL_O + off) = make_uint2(lw01, lw23);
    }
    #pragma unroll
    for (int k2 = 0; k2 < 4; k2++) {
        int t = tid + k2 * 256;
        int row = t >> 4, d4 = (t & 15) * 4;
        uint32_t hw01, lw01, hw23, lw23;
        unpack_pair(vbuf[k2].x, vbuf[k2].y, hw01, lw01);
        unpack_pair(vbuf[k2].z, vbuf[k2].w, hw23, lw23);
        uint32_t off = row * VPB + d4 * 2;
        *(uint2*)(smb + CVH_O + off) = make_uint2(hw01, hw23);
        *(uint2*)(smb + CVL_O + off) = make_uint2(lw01, lw23);
    }
    __syncthreads();

    int i0 = wid * 16;
    int q4i = lane >> 3, rr = lane & 7;
    uint32_t aRow = sb + CKH_O + (8 * (lane >> 4) + rr) * KPB + (i0 + 8 * (q4i & 1)) * 2;
    uint32_t bRow = sb + CVH_O + (8 * (q4i & 1) + rr) * VPB + (8 * (q4i >> 1)) * 2;

    float cS[8][4];
    #pragma unroll
    for (int t8 = 0; t8 < 8; t8++) { cS[t8][0]=0; cS[t8][1]=0; cS[t8][2]=0; cS[t8][3]=0; }

    #pragma unroll
    for (int c0 = 0; c0 < 64; c0 += 16) {
        uint32_t aH[4], aL[4];
        ldsm4t(aRow + c0*KPB,                 aH[0], aH[1], aH[2], aH[3]);
        ldsm4t(aRow + (CKL_O-CKH_O) + c0*KPB, aL[0], aL[1], aL[2], aL[3]);
        uint32_t bH[4][4], bL[4][4];
        #pragma unroll
        for (int nt = 0; nt < 4; nt++) {
            ldsm4t(bRow + c0*VPB + nt*32,                 bH[nt][0], bH[nt][1], bH[nt][2], bH[nt][3]);
            ldsm4t(bRow + (CVL_O-CVH_O) + c0*VPB + nt*32, bL[nt][0], bL[nt][1], bL[nt][2], bL[nt][3]);
        }
        #pragma unroll
        for (int nt = 0; nt < 4; nt++) {
            mma16816(cS[2*nt],   aH, bH[nt][0], bH[nt][1]);
            mma16816(cS[2*nt+1], aH, bH[nt][2], bH[nt][3]);
            mma16816(cS[2*nt],   aH, bL[nt][0], bL[nt][1]);
            mma16816(cS[2*nt+1], aH, bL[nt][2], bL[nt][3]);
            mma16816(cS[2*nt],   aL, bH[nt][0], bH[nt][1]);
            mma16816(cS[2*nt+1], aL, bH[nt][2], bH[nt][3]);
        }
    }

    float* Sp = &g_state[(size_t)blockIdx.x * (Dc * Mc)];
    int m0g = i0 + (lane >> 2);
    int cb  = 2 * (lane & 3);
    #pragma unroll
    for (int t8 = 0; t8 < 8; t8++) {
        int d = cb + 8 * t8;
        *(float2*)&Sp[m0g * 64 + d]       = make_float2(cS[t8][0], cS[t8][1]);
        *(float2*)&Sp[(m0g + 8) * 64 + d] = make_float2(cS[t8][2], cS[t8][3]);
    }

    if (tid < 128) {
        float z = 0.f;
        #pragma unroll
        for (int cc = 0; cc < 64; cc++) z += rec1(kq[cc * Mc + tid]);
        g_ksum[(size_t)blockIdx.x * Mc + tid] = z;
    }
}

// ---------------------------------------------------------------------------
// Kernel 3: exclusive prefix over chunks (latency-optimized).
// State: 2 rounds of 32 batched loads.  ksum: 4 rounds of 16.
// ---------------------------------------------------------------------------
__global__ void prefix_kernel()
{
    int bh = blockIdx.x >> 5, slice = blockIdx.x & 31;
    int e = slice * 256 + threadIdx.x;
    size_t base = (size_t)bh * NCH * (Dc * Mc) + e;
    float acc = 0.f;
    #pragma unroll
    for (int half = 0; half < 2; half++) {
        float v[32];
        size_t b0 = base + (size_t)(half * 32) * (Dc * Mc);
        #pragma unroll
        for (int u = 0; u < 32; u++) v[u] = g_state[b0 + (size_t)u * (Dc * Mc)];
        #pragma unroll
        for (int u = 0; u < 32; u++) {
            ((uint32_t*)g_state)[b0 + (size_t)u * (Dc * Mc)] = pack1(acc);
            acc += v[u];
        }
    }

    if (slice == 0 && threadIdx.x < 128) {
        size_t kb = (size_t)bh * NCH * Mc + threadIdx.x;
        float a2 = 0.f;
        #pragma unroll
        for (int q = 0; q < 4; q++) {
            float t[16];
            size_t b0 = kb + (size_t)(q * 16) * Mc;
            #pragma unroll
            for (int u = 0; u < 16; u++) t[u] = g_ksum[b0 + (size_t)u * Mc];
            #pragma unroll
            for (int u = 0; u < 16; u++) {
                g_ksum[b0 + (size_t)u * Mc] = a2;
                a2 += t[u];
            }
        }
    }
}

// ---------------------------------------------------------------------------
// Kernel 4: out_kernel, 2 CTAs/SM.  K-region unioned with S-region.
// ---------------------------------------------------------------------------
#define QPB 272
#define TPB 144
#define QH_O 0
#define QL_O 17408
#define U_O  34816
#define VH_O 71680
#define VL_O 80896
#define AH_O 90112
#define AL_O 99328
#define KS_O 108544
#define DEN_O 109056
#define OUT_SMEM 109312

__global__ void __launch_bounds__(256, 2)
out_kernel(float* __restrict__ outg)
{
    extern __shared__ __align__(128) char smb[];
    uint32_t sb = smem_u32(smb);
    float* ks_s  = (float*)(smb + KS_O);
    float* den_s = (float*)(smb + DEN_O);

    int tid = threadIdx.x, lane = tid & 31, wid = tid >> 5;
    int bh = blockIdx.x >> 6, c = blockIdx.x & 63;
    int b = bh >> 3, h = bh & 7;

    const uint32_t* qt = g_qp + (size_t)blockIdx.x * (64 * Mc);
    const uint32_t* kt = g_kp + (size_t)blockIdx.x * (64 * Mc);
    const uint4* q4 = (const uint4*)qt;
    const uint4* k4 = (const uint4*)kt;
    const uint4* s4 = (const uint4*)((const uint32_t*)g_state + (size_t)blockIdx.x * (Mc * Dc));
    const uint4* v4 = (const uint4*)(g_vsp + (size_t)blockIdx.x * 4096);

    if (tid < 128) ks_s[tid] = g_ksum[(size_t)blockIdx.x * Mc + tid];

    uint4 sbuf[8];
    #pragma unroll
    for (int k2 = 0; k2 < 8; k2++) sbuf[k2] = s4[tid + k2 * 256];

    {
        uint4 buf[8];
        #pragma unroll
        for (int k2 = 0; k2 < 8; k2++) buf[k2] = q4[tid + k2 * 256];
        #pragma unroll
        for (int k2 = 0; k2 < 8; k2++) {
            int t = tid + k2 * 256;
            int r = t >> 5, m4 = (t & 31) * 4;
            uint32_t hw01, lw01, hw23, lw23;
            unpack_pair(buf[k2].x, buf[k2].y, hw01, lw01);
            unpack_pair(buf[k2].z, buf[k2].w, hw23, lw23);
            uint32_t off = r * QPB + m4 * 2;
            *(uint2*)(smb + QH_O + off) = make_uint2(hw01, hw23);
            *(uint2*)(smb + QL_O + off) = make_uint2(lw01, lw23);
        }
    }
    {
        uint4 buf[8];
        #pragma unroll
        for (int k2 = 0; k2 < 8; k2++) buf[k2] = k4[tid + k2 * 256];
        #pragma unroll
        for (int k2 = 0; k2 < 8; k2++) {
            int t = tid + k2 * 256;
            int r = t >> 5, m4 = (t & 31) * 4;
            uint32_t hw01, lw01, hw23, lw23;
            unpack_pair(buf[k2].x, buf[k2].y, hw01, lw01);
            unpack_pair(buf[k2].z, buf[k2].w, hw23, lw23);
            uint32_t off = r * QPB + m4 * 2;
            *(uint2*)(smb + U_O + off)         = make_uint2(hw01, hw23);
            *(uint2*)(smb + U_O + 17408 + off) = make_uint2(lw01, lw23);
        }
    }
    {
        uint4 buf[4];
        #pragma unroll
        for (int k2 = 0; k2 < 4; k2++) buf[k2] = v4[tid + k2 * 256];
        #pragma unroll
        for (int k2 = 0; k2 < 4; k2++) {
            int t = tid + k2 * 256;
            int row = t >> 4, d4 = (t & 15) * 4;
            uint32_t hw01, lw01, hw23, lw23;
            unpack_pair(buf[k2].x, buf[k2].y, hw01, lw01);
            unpack_pair(buf[k2].z, buf[k2].w, hw23, lw23);
            uint32_t off = row * TPB + d4 * 2;
            *(uint2*)(smb + VH_O + off) = make_uint2(hw01, hw23);
            *(uint2*)(smb + VL_O + off) = make_uint2(lw01, lw23);
        }
    }
    __syncthreads();

    if (tid < 64) {
        const uint4* qr = (const uint4*)(qt + tid * Mc);
        float qd = 0.f;
        #pragma unroll
        for (int m4 = 0; m4 < 32; m4++) {
            uint4 p = qr[m4];
            qd += rec1(p.x) * ks_s[4*m4]   + rec1(p.y) * ks_s[4*m4+1]
                + rec1(p.z) * ks_s[4*m4+2] + rec1(p.w) * ks_s[4*m4+3];
        }
        den_s[tid] = qd;
    }
    // den init must happen-before the atomicAdd rowsum accumulation below.
    __syncthreads();

    int rw = wid & 3, cw = wid >> 2;
    int i0 = 16 * rw, n0 = 32 * cw;
    int q4i = lane >> 3, rr = lane & 7;

    uint32_t aRowQ = sb + QH_O + (i0 + (lane & 15)) * QPB + (lane >> 4) * 16;
    uint32_t bRowK = sb + U_O  + (n0 + 8 * (q4i >> 1) + rr) * QPB + (q4i & 1) * 16;
    uint32_t aRowA = sb + AH_O + (i0 + (lane & 15)) * TPB + (lane >> 4) * 16;
    uint32_t bRowV = sb + VH_O + (8 * (q4i & 1) + rr) * TPB + (n0 + 8 * (q4i >> 1)) * 2;
    uint32_t bRowS = sb + U_O  + (8 * (q4i & 1) + rr) * TPB + (n0 + 8 * (q4i >> 1)) * 2;

    float cA[4][4];
    #pragma unroll
    for (int nt = 0; nt < 4; nt++) { cA[nt][0]=0; cA[nt][1]=0; cA[nt][2]=0; cA[nt][3]=0; }
    #pragma unroll
    for (int k0 = 0; k0 < 128; k0 += 16) {
        uint32_t aH[4], aL[4], bHa[4], bHb[4], bLa[4], bLb[4];
        ldsm4(aRowQ + k0*2,               aH[0], aH[1], aH[2], aH[3]);
        ldsm4(aRowQ + (QL_O-QH_O) + k0*2, aL[0], aL[1], aL[2], aL[3]);
        ldsm4(bRowK + k0*2,               bHa[0], bHa[1], bHa[2], bHa[3]);
        ldsm4(bRowK + 16*QPB + k0*2,      bHb[0], bHb[1], bHb[2], bHb[3]);
        ldsm4(bRowK + 17408 + k0*2,           bLa[0], bLa[1], bLa[2], bLa[3]);
        ldsm4(bRowK + 17408 + 16*QPB + k0*2,  bLb[0], bLb[1], bLb[2], bLb[3]);
        mma16816(cA[0], aH, bHa[0], bHa[1]); mma16816(cA[1], aH, bHa[2], bHa[3]);
        mma16816(cA[2], aH, bHb[0], bHb[1]); mma16816(cA[3], aH, bHb[2], bHb[3]);
        mma16816(cA[0], aH, bLa[0], bLa[1]); mma16816(cA[1], aH, bLa[2], bLa[3]);
        mma16816(cA[2], aH, bLb[0], bLb[1]); mma16816(cA[3], aH, bLb[2], bLb[3]);
        mma16816(cA[0], aL, bHa[0], bHa[1]); mma16816(cA[1], aL, bHa[2], bHa[3]);
        mma16816(cA[2], aL, bHb[0], bHb[1]); mma16816(cA[3], aL, bHb[2], bHb[3]);
    }

    {
        int r0g = i0 + (lane >> 2);
        int cb  = n0 + 2 * (lane & 3);
        float rs0 = 0.f, rs1 = 0.f;
        #pragma unroll
        for (int nt = 0; nt < 4; nt++) {
            int j0 = cb + 8 * nt;
            float x0 = (j0     <= r0g    ) ? cA[nt][0] : 0.f;
            float x1 = (j0 + 1 <= r0g    ) ? cA[nt][1] : 0.f;
            float x2 = (j0     <= r0g + 8) ? cA[nt][2] : 0.f;
            float x3 = (j0 + 1 <= r0g + 8) ? cA[nt][3] : 0.f;
            rs0 += x0 + x1; rs1 += x2 + x3;
            uint32_t h0, l0, h1, l1;
            split2(x0, x1, h0, l0); split2(x2, x3, h1, l1);
            uint32_t o0 = r0g * TPB + j0 * 2, o1 = (r0g + 8) * TPB + j0 * 2;
            *(uint32_t*)(smb + AH_O + o0) = h0; *(uint32_t*)(smb + AL_O + o0) = l0;
            *(uint32_t*)(smb + AH_O + o1) = h1; *(uint32_t*)(smb + AL_O + o1) = l1;
        }
        rs0 += __shfl_xor_sync(0xffffffffu, rs0, 1); rs0 += __shfl_xor_sync(0xffffffffu, rs0, 2);
        rs1 += __shfl_xor_sync(0xffffffffu, rs1, 1); rs1 += __shfl_xor_sync(0xffffffffu, rs1, 2);
        if ((lane & 3) == 0) {
            atomicAdd(&den_s[r0g], rs0);
            atomicAdd(&den_s[r0g + 8], rs1);
        }
    }
    __syncthreads();

    #pragma unroll
    for (int k2 = 0; k2 < 8; k2++) {
        int t = tid + k2 * 256;
        int m = t >> 4, d4 = (t & 15) * 4;
        uint32_t hw01, lw01, hw23, lw23;
        unpack_pair(sbuf[k2].x, sbuf[k2].y, hw01, lw01);
        unpack_pair(sbuf[k2].z, sbuf[k2].w, hw23, lw23);
        uint32_t off = m * TPB + d4 * 2;
        *(uint2*)(smb + U_O + off)         = make_uint2(hw01, hw23);
        *(uint2*)(smb + U_O + 18432 + off) = make_uint2(lw01, lw23);
    }
    __syncthreads();

    float cO[4][4];
    #pragma unroll
    for (int nt = 0; nt < 4; nt++) { cO[nt][0]=0; cO[nt][1]=0; cO[nt][2]=0; cO[nt][3]=0; }
    #pragma unroll
    for (int k0 = 0; k0 < 64; k0 += 16) {
        uint32_t aH[4], aL[4], bHa[4], bHb[4], bLa[4], bLb[4];
        ldsm4(aRowA + k0*2,               aH[0], aH[1], aH[2], aH[3]);
        ldsm4(aRowA + (AL_O-AH_O) + k0*2, aL[0], aL[1], aL[2], aL[3]);
        ldsm4t(bRowV + k0*TPB,                  bHa[0], bHa[1], bHa[2], bHa[3]);
        ldsm4t(bRowV + k0*TPB + 32,             bHb[0], bHb[1], bHb[2], bHb[3]);
        ldsm4t(bRowV + (VL_O-VH_O) + k0*TPB,      bLa[0], bLa[1], bLa[2], bLa[3]);
        ldsm4t(bRowV + (VL_O-VH_O) + k0*TPB + 32, bLb[0], bLb[1], bLb[2], bLb[3]);
        mma16816(cO[0], aH, bHa[0], bHa[1]); mma16816(cO[1], aH, bHa[2], bHa[3]);
        mma16816(cO[2], aH, bHb[0], bHb[1]); mma16816(cO[3], aH, bHb[2], bHb[3]);
        mma16816(cO[0], aL, bHa[0], bHa[1]); mma16816(cO[1], aL, bHa[2], bHa[3]);
        mma16816(cO[2], aL, bHb[0], bHb[1]); mma16816(cO[3], aL, bHb[2], bHb[3]);
        mma16816(cO[0], aH, bLa[0], bLa[1]); mma16816(cO[1], aH, bLa[2], bLa[3]);
        mma16816(cO[2], aH, bLb[0], bLb[1]); mma16816(cO[3], aH, bLb[2], bLb[3]);
    }
    #pragma unroll
    for (int k0 = 0; k0 < 128; k0 += 16) {
        uint32_t aH[4], aL[4], bHa[4], bHb[4], bLa[4], bLb[4];
        ldsm4(aRowQ + k0*2,               aH[0], aH[1], aH[2], aH[3]);
        ldsm4(aRowQ + (QL_O-QH_O) + k0*2, aL[0], aL[1], aL[2], aL[3]);
        ldsm4t(bRowS + k0*TPB,            bHa[0], bHa[1], bHa[2], bHa[3]);
        ldsm4t(bRowS + k0*TPB + 32,       bHb[0], bHb[1], bHb[2], bHb[3]);
        ldsm4t(bRowS + 18432 + k0*TPB,      bLa[0], bLa[1], bLa[2], bLa[3]);
        ldsm4t(bRowS + 18432 + k0*TPB + 32, bLb[0], bLb[1], bLb[2], bLb[3]);
        mma16816(cO[0], aH, bHa[0], bHa[1]); mma16816(cO[1], aH, bHa[2], bHa[3]);
        mma16816(cO[2], aH, bHb[0], bHb[1]); mma16816(cO[3], aH, bHb[2], bHb[3]);
        mma16816(cO[0], aL, bHa[0], bHa[1]); mma16816(cO[1], aL, bHa[2], bHa[3]);
        mma16816(cO[2], aL, bHb[0], bHb[1]); mma16816(cO[3], aL, bHb[2], bHb[3]);
        mma16816(cO[0], aH, bLa[0], bLa[1]); mma16816(cO[1], aH, bLa[2], bLa[3]);
        mma16816(cO[2], aH, bLb[0], bLb[1]); mma16816(cO[3], aH, bLb[2], bLb[3]);
    }

    {
        int r0g = i0 + (lane >> 2);
        int cb  = n0 + 2 * (lane & 3);
        float inv0 = __fdividef(1.f, den_s[r0g]);
        float inv1 = __fdividef(1.f, den_s[r0g + 8]);
        float* orow0 = outg + (((size_t)b * Lc + c*64 + r0g    ) * Hc + h) * Dc;
        float* orow1 = outg + (((size_t)b * Lc + c*64 + r0g + 8) * Hc + h) * Dc;
        #pragma unroll
        for (int nt = 0; nt < 4; nt++) {
            int j0 = cb + 8 * nt;
            *(float2*)(orow0 + j0) = make_float2(cO[nt][0] * inv0, cO[nt][1] * inv0);
            *(float2*)(orow1 + j0) = make_float2(cO[nt][2] * inv1, cO[nt][3] * inv1);
        }
    }
}

// ---------------------------------------------------------------------------
extern "C" void kernel_launch(void* const* d_in, const int* in_sizes, int n_in,
                              void* d_out, int out_size)
{
    const float* q    = (const float*)d_in[0];
    const float* k    = (const float*)d_in[1];
    const float* v    = (const float*)d_in[2];
    const float* proj = (const float*)d_in[3];
    float* out = (float*)d_out;

    cudaFuncSetAttribute(proj_kernel,  cudaFuncAttributeMaxDynamicSharedMemorySize, PJ_SMEM);
    cudaFuncSetAttribute(chunk_kernel, cudaFuncAttributeMaxDynamicSharedMemorySize, CK_SMEM);
    cudaFuncSetAttribute(out_kernel,   cudaFuncAttributeMaxDynamicSharedMemorySize, OUT_SMEM);

    vsplit_kernel<<<BH * NCH, 256>>>(v);
    proj_kernel<<<2048, 256, PJ_SMEM>>>(q, k, proj);
    chunk_kernel<<<BH * NCH, 256, CK_SMEM>>>();
    prefix_kernel<<<BH * 32, 256>>>();
    out_kernel<<<BH * NCH, 256, OUT_SMEM>>>(out);
}